// round 1
// baseline (speedup 1.0000x reference)
#include <cuda_runtime.h>

#define HWSZ  65536
#define CDIM  192
#define NHEADS 8
#define CH    24
#define BSZ   2

// ---------------- scratch (no cudaMalloc allowed) ----------------
__device__ float g_pre_q [(size_t)BSZ * CDIM     * HWSZ];   // 100.7 MB
__device__ float g_pre_kv[(size_t)BSZ * 2 * CDIM * HWSZ];   // 201.3 MB
__device__ float g_v    [(size_t)BSZ * CDIM      * HWSZ];   // 100.7 MB
__device__ float g_gram [BSZ * NHEADS * CH * CH];
__device__ float g_ssq  [BSZ * CDIM];
__device__ float g_ssk  [BSZ * CDIM];
__device__ float g_M    [BSZ * CDIM * CDIM];

// ---------------- f32x2 helpers (Blackwell packed fp32) ----------------
__device__ __forceinline__ unsigned long long pack2(float a, float b) {
    unsigned long long r;
    asm("mov.b64 %0, {%1, %2};" : "=l"(r) : "f"(a), "f"(b));
    return r;
}
__device__ __forceinline__ void fma2(unsigned long long& d,
                                     unsigned long long a, unsigned long long b) {
    asm("fma.rn.f32x2 %0, %1, %2, %3;" : "=l"(d) : "l"(a), "l"(b), "l"(d));
}
__device__ __forceinline__ float2 unpack2(unsigned long long v) {
    float2 f;
    asm("mov.b64 {%0, %1}, %2;" : "=f"(f.x), "=f"(f.y) : "l"(v));
    return f;
}

// ---------------- zero accumulators ----------------
__global__ void zero_stats_kernel(float* gram, float* ssq, float* ssk) {
    int i = blockIdx.x * 256 + threadIdx.x;
    if (i < BSZ * NHEADS * CH * CH) gram[i] = 0.f;
    if (i < BSZ * CDIM) { ssq[i] = 0.f; ssk[i] = 0.f; }
}

// ---------------- GEMM: Y[b][m][n] = sum_k W[b][m][k] * X[b][k][n] ----------------
// K = 192 fixed, N = 65536 per batch. BM=64, BN=128, BK=16, 256 threads,
// each thread computes 4(m) x 8(n) with f32x2-packed accumulators (pairs along n).
__global__ __launch_bounds__(256) void gemm192_kernel(
    const float* __restrict__ Wm, long long wstride_b,
    const float* __restrict__ X,  long long xstride_b,
    float* __restrict__ Y,        long long ystride_b)
{
    __shared__ float As[16][72];    // [k][m], padded for bank-conflict-free stores
    __shared__ float Bs[16][128];   // [k][n]

    const int tid = threadIdx.x;
    const int tx = tid & 15, ty = tid >> 4;
    const int m0 = blockIdx.x * 64;
    const int n0 = blockIdx.y * 128;
    const int b  = blockIdx.z;

    const float* Wb = Wm + (size_t)b * wstride_b;
    const float* Xb = X  + (size_t)b * xstride_b;
    float*       Yb = Y  + (size_t)b * ystride_b;

    const int ar = tid >> 2;          // 0..63  (m row within tile)
    const int ac = (tid & 3) << 2;    // 0,4,8,12 (k col, float4)

    unsigned long long acc[4][4];
#pragma unroll
    for (int i = 0; i < 4; i++)
#pragma unroll
        for (int j = 0; j < 4; j++) acc[i][j] = 0ull;

    for (int k0 = 0; k0 < 192; k0 += 16) {
        float4 a4 = *reinterpret_cast<const float4*>(Wb + (size_t)(m0 + ar) * 192 + k0 + ac);
        As[ac + 0][ar] = a4.x; As[ac + 1][ar] = a4.y;
        As[ac + 2][ar] = a4.z; As[ac + 3][ar] = a4.w;
#pragma unroll
        for (int i = 0; i < 2; i++) {
            int e  = tid + i * 256;
            int br = e >> 5;
            int bc = (e & 31) << 2;
            *reinterpret_cast<float4*>(&Bs[br][bc]) =
                *reinterpret_cast<const float4*>(Xb + (size_t)(k0 + br) * HWSZ + n0 + bc);
        }
        __syncthreads();
#pragma unroll
        for (int kk = 0; kk < 16; kk++) {
            float4 av = *reinterpret_cast<const float4*>(&As[kk][ty << 2]);
            unsigned long long aa[4];
            aa[0] = pack2(av.x, av.x); aa[1] = pack2(av.y, av.y);
            aa[2] = pack2(av.z, av.z); aa[3] = pack2(av.w, av.w);
            ulonglong2 bL = *reinterpret_cast<const ulonglong2*>(&Bs[kk][tx << 2]);
            ulonglong2 bH = *reinterpret_cast<const ulonglong2*>(&Bs[kk][64 + (tx << 2)]);
#pragma unroll
            for (int i = 0; i < 4; i++) {
                fma2(acc[i][0], aa[i], bL.x);
                fma2(acc[i][1], aa[i], bL.y);
                fma2(acc[i][2], aa[i], bH.x);
                fma2(acc[i][3], aa[i], bH.y);
            }
        }
        __syncthreads();
    }

#pragma unroll
    for (int i = 0; i < 4; i++) {
        size_t yb = (size_t)(m0 + (ty << 2) + i) * HWSZ + n0 + (tx << 2);
        float2 f0 = unpack2(acc[i][0]), f1 = unpack2(acc[i][1]);
        *reinterpret_cast<float4*>(Yb + yb) = make_float4(f0.x, f0.y, f1.x, f1.y);
        f0 = unpack2(acc[i][2]); f1 = unpack2(acc[i][3]);
        *reinterpret_cast<float4*>(Yb + yb + 64) = make_float4(f0.x, f0.y, f1.x, f1.y);
    }
}

// ---------------- dwconv3x3 + Gram + norms + v ----------------
__device__ __forceinline__ void load_halo8(float* halo, const float* src, int chBase,
                                           int ty0, int tx0, int tid) {
    for (int i = tid; i < 8 * 324; i += 128) {
        int ch  = i / 324;
        int rem = i - ch * 324;
        int r   = rem / 18;
        int cc  = rem - r * 18;
        int gy = ty0 - 1 + r, gx = tx0 - 1 + cc;
        float vv = 0.f;
        if ((unsigned)gy < 256u && (unsigned)gx < 256u)
            vv = src[(size_t)(chBase + ch) * HWSZ + gy * 256 + gx];
        halo[i] = vv;
    }
}

__device__ __forceinline__ float dw9(const float* hb, const float* w) {
    return hb[0]  * w[0] + hb[1]  * w[1] + hb[2]  * w[2]
         + hb[18] * w[3] + hb[19] * w[4] + hb[20] * w[5]
         + hb[36] * w[6] + hb[37] * w[7] + hb[38] * w[8];
}

// grid (16,16,2): 16x16-pixel tile per CTA, 128 threads (2 px each).
// smem: halo[8*324] + qs[256*26] + ks[256*26]  (dynamic, 63.6 KB)
__global__ __launch_bounds__(128) void dw_reduce_kernel(
    const float* __restrict__ pre_q, const float* __restrict__ pre_kv,
    const float* __restrict__ wq_dw, const float* __restrict__ wkv_dw,
    float* __restrict__ vout, float* __restrict__ ssq, float* __restrict__ ssk,
    float* __restrict__ gram)
{
    extern __shared__ float sm[];
    float* halo = sm;                  // 2592 floats
    float* qs   = sm + 2592;           // 256*26
    float* ks   = qs + 256 * 26;       // 256*26

    const int tid = threadIdx.x;
    const int b   = blockIdx.z;
    const int tx0 = blockIdx.x * 16;
    const int ty0 = blockIdx.y * 16;
    const float* srcq  = pre_q  + (size_t)b * CDIM * HWSZ;
    const float* srckv = pre_kv + (size_t)b * 2 * CDIM * HWSZ;

    for (int h = 0; h < NHEADS; h++) {
        const int cb = h * CH;

        // ---- q channels -> qs ----
        for (int g = 0; g < 3; g++) {
            load_halo8(halo, srcq, cb + g * 8, ty0, tx0, tid);
            __syncthreads();
            for (int cc = 0; cc < 8; cc++) {
                int c = g * 8 + cc;
                const float* w = wq_dw + (size_t)(cb + c) * 9;
                float wr[9];
#pragma unroll
                for (int j = 0; j < 9; j++) wr[j] = __ldg(w + j);
#pragma unroll
                for (int e = 0; e < 2; e++) {
                    int p = tid + e * 128;
                    int py = p >> 4, px = p & 15;
                    qs[p * 26 + c] = dw9(halo + cc * 324 + py * 18 + px, wr);
                }
            }
            __syncthreads();
        }
        // ---- k channels -> ks ----
        for (int g = 0; g < 3; g++) {
            load_halo8(halo, srckv, cb + g * 8, ty0, tx0, tid);
            __syncthreads();
            for (int cc = 0; cc < 8; cc++) {
                int c = g * 8 + cc;
                const float* w = wkv_dw + (size_t)(cb + c) * 9;
                float wr[9];
#pragma unroll
                for (int j = 0; j < 9; j++) wr[j] = __ldg(w + j);
#pragma unroll
                for (int e = 0; e < 2; e++) {
                    int p = tid + e * 128;
                    int py = p >> 4, px = p & 15;
                    ks[p * 26 + c] = dw9(halo + cc * 324 + py * 18 + px, wr);
                }
            }
            __syncthreads();
        }

        // ---- sum of squares (block-reduced, 1 atomic per channel) ----
        if (tid < 96) {
            int c = tid % 24, qtr = tid / 24;
            float s = 0.f, s2 = 0.f;
            for (int p = qtr * 64; p < qtr * 64 + 64; p++) {
                float v1 = qs[p * 26 + c]; s  += v1 * v1;
                float v2 = ks[p * 26 + c]; s2 += v2 * v2;
            }
            halo[tid] = s; halo[96 + tid] = s2;
        }
        __syncthreads();
        if (tid < 24) {
            float t = halo[tid] + halo[24 + tid] + halo[48 + tid] + halo[72 + tid];
            atomicAdd(&ssq[b * CDIM + cb + tid], t);
            float t2 = halo[96 + tid] + halo[120 + tid] + halo[144 + tid] + halo[168 + tid];
            atomicAdd(&ssk[b * CDIM + cb + tid], t2);
        }

        // ---- Gram: 24x24 = 144 tasks of 2x2, over 256 pixels ----
        for (int t = tid; t < 144; t += 128) {
            int c0 = (t / 12) * 2, d0 = (t % 12) * 2;
            float a00 = 0.f, a01 = 0.f, a10 = 0.f, a11 = 0.f;
#pragma unroll 4
            for (int p = 0; p < 256; p++) {
                float2 qv = *reinterpret_cast<const float2*>(&qs[p * 26 + c0]);
                float2 kv = *reinterpret_cast<const float2*>(&ks[p * 26 + d0]);
                a00 += qv.x * kv.x; a01 += qv.x * kv.y;
                a10 += qv.y * kv.x; a11 += qv.y * kv.y;
            }
            float* gb = gram + (((size_t)b * NHEADS + h) * CH + c0) * CH + d0;
            atomicAdd(gb,          a00); atomicAdd(gb + 1,      a01);
            atomicAdd(gb + CH,     a10); atomicAdd(gb + CH + 1, a11);
        }
        __syncthreads();

        // ---- v channels -> global ----
        for (int g = 0; g < 3; g++) {
            load_halo8(halo, srckv, CDIM + cb + g * 8, ty0, tx0, tid);
            __syncthreads();
            for (int cc = 0; cc < 8; cc++) {
                int c = g * 8 + cc;
                const float* w = wkv_dw + (size_t)(CDIM + cb + c) * 9;
                float wr[9];
#pragma unroll
                for (int j = 0; j < 9; j++) wr[j] = __ldg(w + j);
#pragma unroll
                for (int e = 0; e < 2; e++) {
                    int p = tid + e * 128;
                    int py = p >> 4, px = p & 15;
                    float val = dw9(halo + cc * 324 + py * 18 + px, wr);
                    vout[((size_t)b * CDIM + cb + c) * HWSZ + (ty0 + py) * 256 + (tx0 + px)] = val;
                }
            }
            __syncthreads();
        }
    }
}

// ---------------- softmax + M = Wproj * blockdiag(attn) ----------------
__global__ __launch_bounds__(256) void attn_proj_kernel(
    const float* __restrict__ gram, const float* __restrict__ ssq,
    const float* __restrict__ ssk,  const float* __restrict__ temp,
    const float* __restrict__ wproj, float* __restrict__ Mout)
{
    __shared__ float at[192][25];
    __shared__ float nk_s[192];
    const int b = blockIdx.x, tid = threadIdx.x;

    if (tid < 192) nk_s[tid] = fmaxf(sqrtf(ssk[b * CDIM + tid]), 1e-12f);
    __syncthreads();

    if (tid < 192) {
        int h = tid / 24, c = tid % 24;
        float nq = fmaxf(sqrtf(ssq[b * CDIM + tid]), 1e-12f);
        float tv = temp[h];
        const float* gr = gram + (((size_t)b * NHEADS + h) * CH + c) * CH;
        float vals[24];
        float mx = -1e30f;
#pragma unroll
        for (int d = 0; d < 24; d++) {
            float v = gr[d] / (nq * nk_s[h * 24 + d]) * tv;
            vals[d] = v;
            mx = fmaxf(mx, v);
        }
        float s = 0.f;
#pragma unroll
        for (int d = 0; d < 24; d++) { vals[d] = expf(vals[d] - mx); s += vals[d]; }
        float inv = 1.f / s;
#pragma unroll
        for (int d = 0; d < 24; d++) at[tid][d] = vals[d] * inv;
    }
    __syncthreads();

    for (int idx = tid; idx < 192 * 192; idx += 256) {
        int o = idx / 192, dg = idx % 192;
        int h = dg / 24, d = dg % 24;
        float s = 0.f;
#pragma unroll
        for (int c = 0; c < 24; c++)
            s += wproj[o * 192 + h * 24 + c] * at[h * 24 + c][d];
        Mout[(size_t)b * CDIM * CDIM + idx] = s;
    }
}

// ---------------- launch ----------------
extern "C" void kernel_launch(void* const* d_in, const int* in_sizes, int n_in,
                              void* d_out, int out_size) {
    const float* x      = (const float*)d_in[0];
    const float* x_ref  = (const float*)d_in[1];
    const float* wq     = (const float*)d_in[2];
    const float* wq_dw  = (const float*)d_in[3];
    const float* wkv    = (const float*)d_in[4];
    const float* wkv_dw = (const float*)d_in[5];
    const float* wproj  = (const float*)d_in[6];
    const float* temp   = (const float*)d_in[7];
    float* out = (float*)d_out;

    float *pre_q, *pre_kv, *vbuf, *gram, *ssq, *ssk, *Mm;
    cudaGetSymbolAddress((void**)&pre_q,  g_pre_q);
    cudaGetSymbolAddress((void**)&pre_kv, g_pre_kv);
    cudaGetSymbolAddress((void**)&vbuf,   g_v);
    cudaGetSymbolAddress((void**)&gram,   g_gram);
    cudaGetSymbolAddress((void**)&ssq,    g_ssq);
    cudaGetSymbolAddress((void**)&ssk,    g_ssk);
    cudaGetSymbolAddress((void**)&Mm,     g_M);

    const int smem2 = (2592 + 2 * 256 * 26) * (int)sizeof(float);  // 63616 B
    cudaFuncSetAttribute(dw_reduce_kernel,
                         cudaFuncAttributeMaxDynamicSharedMemorySize, smem2);

    zero_stats_kernel<<<36, 256>>>(gram, ssq, ssk);

    // pre_q = Wq @ x        (M=192)
    gemm192_kernel<<<dim3(3, 512, BSZ), 256>>>(
        wq, 0LL, x, (long long)CDIM * HWSZ, pre_q, (long long)CDIM * HWSZ);
    // pre_kv = Wkv @ x_ref  (M=384)
    gemm192_kernel<<<dim3(6, 512, BSZ), 256>>>(
        wkv, 0LL, x_ref, (long long)CDIM * HWSZ, pre_kv, (long long)2 * CDIM * HWSZ);

    // dwconv + Gram + norms + v
    dw_reduce_kernel<<<dim3(16, 16, BSZ), 128, smem2>>>(
        pre_q, pre_kv, wq_dw, wkv_dw, vbuf, ssq, ssk, gram);

    // softmax + fold projection: M_b = Wproj * blockdiag(attn_b)
    attn_proj_kernel<<<BSZ, 256>>>(gram, ssq, ssk, temp, wproj, Mm);

    // out = M_b @ v   (M=192, per-batch W)
    gemm192_kernel<<<dim3(3, 512, BSZ), 256>>>(
        Mm, (long long)CDIM * CDIM, vbuf, (long long)CDIM * HWSZ,
        out, (long long)CDIM * HWSZ);
}

// round 2
// speedup vs baseline: 1.3821x; 1.3821x over previous
#include <cuda_runtime.h>

#define HWSZ  65536
#define CDIM  192
#define NHEADS 8
#define CH    24
#define BSZ   2
#define QP    257   // channel-major pixel stride (odd => conflict-free)

// ---------------- scratch (no cudaMalloc allowed) ----------------
__device__ float g_pre_q [(size_t)BSZ * CDIM     * HWSZ];   // 100.7 MB
__device__ float g_pre_kv[(size_t)BSZ * 2 * CDIM * HWSZ];   // 201.3 MB
__device__ float g_v    [(size_t)BSZ * CDIM      * HWSZ];   // 100.7 MB
__device__ float g_gram [BSZ * NHEADS * CH * CH];
__device__ float g_ssq  [BSZ * CDIM];
__device__ float g_ssk  [BSZ * CDIM];
__device__ float g_M    [BSZ * CDIM * CDIM];

// ---------------- f32x2 helpers (Blackwell packed fp32) ----------------
__device__ __forceinline__ unsigned long long pack2(float a, float b) {
    unsigned long long r;
    asm("mov.b64 %0, {%1, %2};" : "=l"(r) : "f"(a), "f"(b));
    return r;
}
__device__ __forceinline__ void fma2(unsigned long long& d,
                                     unsigned long long a, unsigned long long b) {
    asm("fma.rn.f32x2 %0, %1, %2, %3;" : "=l"(d) : "l"(a), "l"(b), "l"(d));
}
__device__ __forceinline__ float2 unpack2(unsigned long long v) {
    float2 f;
    asm("mov.b64 {%0, %1}, %2;" : "=f"(f.x), "=f"(f.y) : "l"(v));
    return f;
}

// ---------------- zero accumulators ----------------
__global__ void zero_stats_kernel(float* gram, float* ssq, float* ssk) {
    int i = blockIdx.x * 256 + threadIdx.x;
    if (i < BSZ * NHEADS * CH * CH) gram[i] = 0.f;
    if (i < BSZ * CDIM) { ssq[i] = 0.f; ssk[i] = 0.f; }
}

// ---------------- GEMM: Y[b][m][n] = sum_k W[b][m][k] * X[b][k][n] ----------------
// K = 192 fixed, N = 65536 per batch. BM=64, BN=128, BK=16, 256 threads,
// each thread computes 4(m) x 8(n) with f32x2-packed accumulators (pairs along n).
__global__ __launch_bounds__(256) void gemm192_kernel(
    const float* __restrict__ Wm, long long wstride_b,
    const float* __restrict__ X,  long long xstride_b,
    float* __restrict__ Y,        long long ystride_b)
{
    __shared__ float As[16][72];    // [k][m], padded for bank-conflict-free stores
    __shared__ float Bs[16][128];   // [k][n]

    const int tid = threadIdx.x;
    const int tx = tid & 15, ty = tid >> 4;
    const int m0 = blockIdx.x * 64;
    const int n0 = blockIdx.y * 128;
    const int b  = blockIdx.z;

    const float* Wb = Wm + (size_t)b * wstride_b;
    const float* Xb = X  + (size_t)b * xstride_b;
    float*       Yb = Y  + (size_t)b * ystride_b;

    const int ar = tid >> 2;          // 0..63  (m row within tile)
    const int ac = (tid & 3) << 2;    // 0,4,8,12 (k col, float4)

    unsigned long long acc[4][4];
#pragma unroll
    for (int i = 0; i < 4; i++)
#pragma unroll
        for (int j = 0; j < 4; j++) acc[i][j] = 0ull;

    for (int k0 = 0; k0 < 192; k0 += 16) {
        float4 a4 = *reinterpret_cast<const float4*>(Wb + (size_t)(m0 + ar) * 192 + k0 + ac);
        As[ac + 0][ar] = a4.x; As[ac + 1][ar] = a4.y;
        As[ac + 2][ar] = a4.z; As[ac + 3][ar] = a4.w;
#pragma unroll
        for (int i = 0; i < 2; i++) {
            int e  = tid + i * 256;
            int br = e >> 5;
            int bc = (e & 31) << 2;
            *reinterpret_cast<float4*>(&Bs[br][bc]) =
                *reinterpret_cast<const float4*>(Xb + (size_t)(k0 + br) * HWSZ + n0 + bc);
        }
        __syncthreads();
#pragma unroll
        for (int kk = 0; kk < 16; kk++) {
            float4 av = *reinterpret_cast<const float4*>(&As[kk][ty << 2]);
            unsigned long long aa[4];
            aa[0] = pack2(av.x, av.x); aa[1] = pack2(av.y, av.y);
            aa[2] = pack2(av.z, av.z); aa[3] = pack2(av.w, av.w);
            ulonglong2 bL = *reinterpret_cast<const ulonglong2*>(&Bs[kk][tx << 2]);
            ulonglong2 bH = *reinterpret_cast<const ulonglong2*>(&Bs[kk][64 + (tx << 2)]);
#pragma unroll
            for (int i = 0; i < 4; i++) {
                fma2(acc[i][0], aa[i], bL.x);
                fma2(acc[i][1], aa[i], bL.y);
                fma2(acc[i][2], aa[i], bH.x);
                fma2(acc[i][3], aa[i], bH.y);
            }
        }
        __syncthreads();
    }

#pragma unroll
    for (int i = 0; i < 4; i++) {
        size_t yb = (size_t)(m0 + (ty << 2) + i) * HWSZ + n0 + (tx << 2);
        float2 f0 = unpack2(acc[i][0]), f1 = unpack2(acc[i][1]);
        *reinterpret_cast<float4*>(Yb + yb) = make_float4(f0.x, f0.y, f1.x, f1.y);
        f0 = unpack2(acc[i][2]); f1 = unpack2(acc[i][3]);
        *reinterpret_cast<float4*>(Yb + yb + 64) = make_float4(f0.x, f0.y, f1.x, f1.y);
    }
}

// ---------------- dwconv3x3 + Gram + norms + v (head-parallel) ----------------
__device__ __forceinline__ void load_halo8_256(float* halo, const float* src, int chBase,
                                               int ty0, int tx0, int tid) {
    for (int i = tid; i < 8 * 324; i += 256) {
        int ch  = i / 324;
        int rem = i - ch * 324;
        int r   = rem / 18;
        int cc  = rem - r * 18;
        int gy = ty0 - 1 + r, gx = tx0 - 1 + cc;
        float vv = 0.f;
        if ((unsigned)gy < 256u && (unsigned)gx < 256u)
            vv = src[(size_t)(chBase + ch) * HWSZ + gy * 256 + gx];
        halo[i] = vv;
    }
}

__device__ __forceinline__ float dw9(const float* hb, const float* w) {
    return hb[0]  * w[0] + hb[1]  * w[1] + hb[2]  * w[2]
         + hb[18] * w[3] + hb[19] * w[4] + hb[20] * w[5]
         + hb[36] * w[6] + hb[37] * w[7] + hb[38] * w[8];
}

// grid (16, 16, B*NHEADS): one (head, 16x16-pixel tile) per CTA, 256 threads (1 px each).
// smem: halo[8*324] + qs[24*QP] + ks[24*QP]  (dynamic, 59712 B -> 3 CTAs/SM)
__global__ __launch_bounds__(256) void dw_reduce_kernel(
    const float* __restrict__ pre_q, const float* __restrict__ pre_kv,
    const float* __restrict__ wq_dw, const float* __restrict__ wkv_dw,
    float* __restrict__ vout, float* __restrict__ ssq, float* __restrict__ ssk,
    float* __restrict__ gram)
{
    extern __shared__ float sm[];
    float* halo = sm;                  // 2592 floats
    float* qs   = sm + 2592;           // 24*QP, channel-major
    float* ks   = qs + 24 * QP;

    const int tid = threadIdx.x;
    const int b   = blockIdx.z >> 3;
    const int h   = blockIdx.z & 7;
    const int cb  = h * CH;
    const int tx0 = blockIdx.x * 16;
    const int ty0 = blockIdx.y * 16;
    const int px  = tid & 15, py = tid >> 4;
    const int hbase = py * 18 + px;

    const float* srcq  = pre_q  + (size_t)b * CDIM * HWSZ;
    const float* srckv = pre_kv + (size_t)b * 2 * CDIM * HWSZ;

    // ---- q channels -> qs (channel-major) ----
#pragma unroll 1
    for (int g = 0; g < 3; g++) {
        load_halo8_256(halo, srcq, cb + g * 8, ty0, tx0, tid);
        __syncthreads();
#pragma unroll
        for (int cc = 0; cc < 8; cc++) {
            int c = g * 8 + cc;
            const float* w = wq_dw + (size_t)(cb + c) * 9;
            float wr[9];
#pragma unroll
            for (int j = 0; j < 9; j++) wr[j] = __ldg(w + j);
            qs[c * QP + tid] = dw9(halo + cc * 324 + hbase, wr);
        }
        __syncthreads();
    }
    // ---- k channels -> ks ----
#pragma unroll 1
    for (int g = 0; g < 3; g++) {
        load_halo8_256(halo, srckv, cb + g * 8, ty0, tx0, tid);
        __syncthreads();
#pragma unroll
        for (int cc = 0; cc < 8; cc++) {
            int c = g * 8 + cc;
            const float* w = wkv_dw + (size_t)(cb + c) * 9;
            float wr[9];
#pragma unroll
            for (int j = 0; j < 9; j++) wr[j] = __ldg(w + j);
            ks[c * QP + tid] = dw9(halo + cc * 324 + hbase, wr);
        }
        __syncthreads();
    }

    // ---- sum of squares: 24 channels x 8 pixel-slices, shfl-reduced ----
    if (tid < 192) {
        int c = tid >> 3, s = tid & 7;
        float sq = 0.f, sk = 0.f;
#pragma unroll 8
        for (int i = 0; i < 32; i++) {
            int p = s + (i << 3);
            float a = qs[c * QP + p]; sq += a * a;
            float k2 = ks[c * QP + p]; sk += k2 * k2;
        }
#pragma unroll
        for (int off = 1; off < 8; off <<= 1) {
            sq += __shfl_xor_sync(0xffffffffu, sq, off);
            sk += __shfl_xor_sync(0xffffffffu, sk, off);
        }
        if (s == 0) {
            atomicAdd(&ssq[b * CDIM + cb + c], sq);
            atomicAdd(&ssk[b * CDIM + cb + c], sk);
        }
    }

    // ---- Gram: 36 tasks of 4x4 entries x 8 pixel-slices (strided), shfl-reduced ----
#pragma unroll 1
    for (int t = tid; t < 288; t += 256) {
        int e = t >> 3, s = t & 7;
        int c0 = (e / 6) * 4, d0 = (e % 6) * 4;
        float acc[16];
#pragma unroll
        for (int j = 0; j < 16; j++) acc[j] = 0.f;
#pragma unroll 4
        for (int i = 0; i < 32; i++) {
            int p = s + (i << 3);
            float q0 = qs[(c0 + 0) * QP + p], q1 = qs[(c0 + 1) * QP + p];
            float q2 = qs[(c0 + 2) * QP + p], q3 = qs[(c0 + 3) * QP + p];
            float k0 = ks[(d0 + 0) * QP + p], k1 = ks[(d0 + 1) * QP + p];
            float k2 = ks[(d0 + 2) * QP + p], k3 = ks[(d0 + 3) * QP + p];
            acc[0]  += q0 * k0; acc[1]  += q0 * k1; acc[2]  += q0 * k2; acc[3]  += q0 * k3;
            acc[4]  += q1 * k0; acc[5]  += q1 * k1; acc[6]  += q1 * k2; acc[7]  += q1 * k3;
            acc[8]  += q2 * k0; acc[9]  += q2 * k1; acc[10] += q2 * k2; acc[11] += q2 * k3;
            acc[12] += q3 * k0; acc[13] += q3 * k1; acc[14] += q3 * k2; acc[15] += q3 * k3;
        }
#pragma unroll
        for (int off = 1; off < 8; off <<= 1)
#pragma unroll
            for (int j = 0; j < 16; j++)
                acc[j] += __shfl_xor_sync(0xffffffffu, acc[j], off);
        if (s == 0) {
            float* gb = gram + (((size_t)b * NHEADS + h) * CH + c0) * CH + d0;
#pragma unroll
            for (int jq = 0; jq < 4; jq++)
#pragma unroll
                for (int jk = 0; jk < 4; jk++)
                    atomicAdd(&gb[jq * CH + jk], acc[jq * 4 + jk]);
        }
    }

    // ---- v channels -> global ----
#pragma unroll 1
    for (int g = 0; g < 3; g++) {
        load_halo8_256(halo, srckv, CDIM + cb + g * 8, ty0, tx0, tid);
        __syncthreads();
#pragma unroll
        for (int cc = 0; cc < 8; cc++) {
            int c = g * 8 + cc;
            const float* w = wkv_dw + (size_t)(CDIM + cb + c) * 9;
            float wr[9];
#pragma unroll
            for (int j = 0; j < 9; j++) wr[j] = __ldg(w + j);
            float val = dw9(halo + cc * 324 + hbase, wr);
            vout[((size_t)b * CDIM + cb + c) * HWSZ + (ty0 + py) * 256 + (tx0 + px)] = val;
        }
        __syncthreads();
    }
}

// ---------------- softmax + M = Wproj * blockdiag(attn) ----------------
__global__ __launch_bounds__(256) void attn_proj_kernel(
    const float* __restrict__ gram, const float* __restrict__ ssq,
    const float* __restrict__ ssk,  const float* __restrict__ temp,
    const float* __restrict__ wproj, float* __restrict__ Mout)
{
    __shared__ float at[192][25];
    __shared__ float nk_s[192];
    const int b = blockIdx.x, tid = threadIdx.x;

    if (tid < 192) nk_s[tid] = fmaxf(sqrtf(ssk[b * CDIM + tid]), 1e-12f);
    __syncthreads();

    if (tid < 192) {
        int h = tid / 24, c = tid % 24;
        float nq = fmaxf(sqrtf(ssq[b * CDIM + tid]), 1e-12f);
        float tv = temp[h];
        const float* gr = gram + (((size_t)b * NHEADS + h) * CH + c) * CH;
        float vals[24];
        float mx = -1e30f;
#pragma unroll
        for (int d = 0; d < 24; d++) {
            float v = gr[d] / (nq * nk_s[h * 24 + d]) * tv;
            vals[d] = v;
            mx = fmaxf(mx, v);
        }
        float s = 0.f;
#pragma unroll
        for (int d = 0; d < 24; d++) { vals[d] = expf(vals[d] - mx); s += vals[d]; }
        float inv = 1.f / s;
#pragma unroll
        for (int d = 0; d < 24; d++) at[tid][d] = vals[d] * inv;
    }
    __syncthreads();

    for (int idx = tid; idx < 192 * 192; idx += 256) {
        int o = idx / 192, dg = idx % 192;
        int h = dg / 24, d = dg % 24;
        float s = 0.f;
#pragma unroll
        for (int c = 0; c < 24; c++)
            s += wproj[o * 192 + h * 24 + c] * at[h * 24 + c][d];
        Mout[(size_t)b * CDIM * CDIM + idx] = s;
    }
}

// ---------------- launch ----------------
extern "C" void kernel_launch(void* const* d_in, const int* in_sizes, int n_in,
                              void* d_out, int out_size) {
    const float* x      = (const float*)d_in[0];
    const float* x_ref  = (const float*)d_in[1];
    const float* wq     = (const float*)d_in[2];
    const float* wq_dw  = (const float*)d_in[3];
    const float* wkv    = (const float*)d_in[4];
    const float* wkv_dw = (const float*)d_in[5];
    const float* wproj  = (const float*)d_in[6];
    const float* temp   = (const float*)d_in[7];
    float* out = (float*)d_out;

    float *pre_q, *pre_kv, *vbuf, *gram, *ssq, *ssk, *Mm;
    cudaGetSymbolAddress((void**)&pre_q,  g_pre_q);
    cudaGetSymbolAddress((void**)&pre_kv, g_pre_kv);
    cudaGetSymbolAddress((void**)&vbuf,   g_v);
    cudaGetSymbolAddress((void**)&gram,   g_gram);
    cudaGetSymbolAddress((void**)&ssq,    g_ssq);
    cudaGetSymbolAddress((void**)&ssk,    g_ssk);
    cudaGetSymbolAddress((void**)&Mm,     g_M);

    const int smem2 = (2592 + 2 * 24 * QP) * (int)sizeof(float);  // 59712 B
    cudaFuncSetAttribute(dw_reduce_kernel,
                         cudaFuncAttributeMaxDynamicSharedMemorySize, smem2);

    zero_stats_kernel<<<36, 256>>>(gram, ssq, ssk);

    // pre_q = Wq @ x        (M=192)
    gemm192_kernel<<<dim3(3, 512, BSZ), 256>>>(
        wq, 0LL, x, (long long)CDIM * HWSZ, pre_q, (long long)CDIM * HWSZ);
    // pre_kv = Wkv @ x_ref  (M=384)
    gemm192_kernel<<<dim3(6, 512, BSZ), 256>>>(
        wkv, 0LL, x_ref, (long long)CDIM * HWSZ, pre_kv, (long long)2 * CDIM * HWSZ);

    // dwconv + Gram + norms + v  (head-parallel)
    dw_reduce_kernel<<<dim3(16, 16, BSZ * NHEADS), 256, smem2>>>(
        pre_q, pre_kv, wq_dw, wkv_dw, vbuf, ssq, ssk, gram);

    // softmax + fold projection: M_b = Wproj * blockdiag(attn_b)
    attn_proj_kernel<<<BSZ, 256>>>(gram, ssq, ssk, temp, wproj, Mm);

    // out = M_b @ v   (M=192, per-batch W)
    gemm192_kernel<<<dim3(3, 512, BSZ), 256>>>(
        Mm, (long long)CDIM * CDIM, vbuf, (long long)CDIM * HWSZ,
        out, (long long)CDIM * HWSZ);
}

// round 3
// speedup vs baseline: 1.5148x; 1.0960x over previous
#include <cuda_runtime.h>

#define HWSZ  65536
#define CDIM  192
#define NHEADS 8
#define CH    24
#define BSZ   2
#define QP2   260   // qs/ks pixel stride (multiple of 4 for float4)

// ---------------- scratch (no cudaMalloc allowed) ----------------
__device__ float g_pre_q [(size_t)BSZ * CDIM     * HWSZ];   // 100.7 MB
__device__ float g_pre_kv[(size_t)BSZ * 2 * CDIM * HWSZ];   // 201.3 MB
__device__ float g_v    [(size_t)BSZ * CDIM      * HWSZ];   // 100.7 MB
__device__ float g_gram [BSZ * NHEADS * CH * CH];
__device__ float g_ssq  [BSZ * CDIM];
__device__ float g_ssk  [BSZ * CDIM];
__device__ float g_M    [BSZ * CDIM * CDIM];

// ---------------- f32x2 helpers (Blackwell packed fp32) ----------------
__device__ __forceinline__ unsigned long long pack2(float a, float b) {
    unsigned long long r;
    asm("mov.b64 %0, {%1, %2};" : "=l"(r) : "f"(a), "f"(b));
    return r;
}
__device__ __forceinline__ void fma2(unsigned long long& d,
                                     unsigned long long a, unsigned long long b) {
    asm("fma.rn.f32x2 %0, %1, %2, %3;" : "=l"(d) : "l"(a), "l"(b), "l"(d));
}
__device__ __forceinline__ float2 unpack2(unsigned long long v) {
    float2 f;
    asm("mov.b64 {%0, %1}, %2;" : "=f"(f.x), "=f"(f.y) : "l"(v));
    return f;
}

// ---------------- zero accumulators ----------------
__global__ void zero_stats_kernel(float* gram, float* ssq, float* ssk) {
    int i = blockIdx.x * 256 + threadIdx.x;
    if (i < BSZ * NHEADS * CH * CH) gram[i] = 0.f;
    if (i < BSZ * CDIM) { ssq[i] = 0.f; ssk[i] = 0.f; }
}

// ---------------- GEMM: Y[b][m][n] = sum_k W[b][m][k] * X[b][k][n] ----------------
__global__ __launch_bounds__(256) void gemm192_kernel(
    const float* __restrict__ Wm, long long wstride_b,
    const float* __restrict__ X,  long long xstride_b,
    float* __restrict__ Y,        long long ystride_b)
{
    __shared__ float As[16][72];
    __shared__ float Bs[16][128];

    const int tid = threadIdx.x;
    const int tx = tid & 15, ty = tid >> 4;
    const int m0 = blockIdx.x * 64;
    const int n0 = blockIdx.y * 128;
    const int b  = blockIdx.z;

    const float* Wb = Wm + (size_t)b * wstride_b;
    const float* Xb = X  + (size_t)b * xstride_b;
    float*       Yb = Y  + (size_t)b * ystride_b;

    const int ar = tid >> 2;
    const int ac = (tid & 3) << 2;

    unsigned long long acc[4][4];
#pragma unroll
    for (int i = 0; i < 4; i++)
#pragma unroll
        for (int j = 0; j < 4; j++) acc[i][j] = 0ull;

    for (int k0 = 0; k0 < 192; k0 += 16) {
        float4 a4 = *reinterpret_cast<const float4*>(Wb + (size_t)(m0 + ar) * 192 + k0 + ac);
        As[ac + 0][ar] = a4.x; As[ac + 1][ar] = a4.y;
        As[ac + 2][ar] = a4.z; As[ac + 3][ar] = a4.w;
#pragma unroll
        for (int i = 0; i < 2; i++) {
            int e  = tid + i * 256;
            int br = e >> 5;
            int bc = (e & 31) << 2;
            *reinterpret_cast<float4*>(&Bs[br][bc]) =
                *reinterpret_cast<const float4*>(Xb + (size_t)(k0 + br) * HWSZ + n0 + bc);
        }
        __syncthreads();
#pragma unroll
        for (int kk = 0; kk < 16; kk++) {
            float4 av = *reinterpret_cast<const float4*>(&As[kk][ty << 2]);
            unsigned long long aa[4];
            aa[0] = pack2(av.x, av.x); aa[1] = pack2(av.y, av.y);
            aa[2] = pack2(av.z, av.z); aa[3] = pack2(av.w, av.w);
            ulonglong2 bL = *reinterpret_cast<const ulonglong2*>(&Bs[kk][tx << 2]);
            ulonglong2 bH = *reinterpret_cast<const ulonglong2*>(&Bs[kk][64 + (tx << 2)]);
#pragma unroll
            for (int i = 0; i < 4; i++) {
                fma2(acc[i][0], aa[i], bL.x);
                fma2(acc[i][1], aa[i], bL.y);
                fma2(acc[i][2], aa[i], bH.x);
                fma2(acc[i][3], aa[i], bH.y);
            }
        }
        __syncthreads();
    }

#pragma unroll
    for (int i = 0; i < 4; i++) {
        size_t yb = (size_t)(m0 + (ty << 2) + i) * HWSZ + n0 + (tx << 2);
        float2 f0 = unpack2(acc[i][0]), f1 = unpack2(acc[i][1]);
        *reinterpret_cast<float4*>(Yb + yb) = make_float4(f0.x, f0.y, f1.x, f1.y);
        f0 = unpack2(acc[i][2]); f1 = unpack2(acc[i][3]);
        *reinterpret_cast<float4*>(Yb + yb + 64) = make_float4(f0.x, f0.y, f1.x, f1.y);
    }
}

// ---------------- dwconv3x3 + Gram + norms + v (head-parallel, vectorized) ----------------
// halo layout: 8 channels x 18 rows x stride 20 (col c holds gx = tx0-1+c)
__device__ __forceinline__ void load_halo8v(float* halo, const float* __restrict__ src,
                                            int chBase, int ty0, int tx0, int tid) {
    for (int i = tid; i < 8 * 324; i += 256) {
        int ch  = i / 324;
        int rem = i - ch * 324;
        int r   = rem / 18;
        int cc  = rem - r * 18;
        int gy = ty0 - 1 + r, gx = tx0 - 1 + cc;
        float vv = 0.f;
        if ((unsigned)gy < 256u && (unsigned)gx < 256u)
            vv = src[(size_t)(chBase + ch) * HWSZ + gy * 256 + gx];
        halo[ch * 360 + r * 20 + cc] = vv;
    }
}

// Compute 2x2 quad of dwconv outputs from a 4x4 tap region fetched as 8 x float2.
__device__ __forceinline__ float4 dw_quad(const float* hb, const float* wr) {
    float r4[4][4];
#pragma unroll
    for (int r = 0; r < 4; r++) {
        float2 a  = *reinterpret_cast<const float2*>(hb + r * 20);
        float2 b2 = *reinterpret_cast<const float2*>(hb + r * 20 + 2);
        r4[r][0] = a.x; r4[r][1] = a.y; r4[r][2] = b2.x; r4[r][3] = b2.y;
    }
    float ox = 0.f, oy = 0.f, oz = 0.f, ow = 0.f;
#pragma unroll
    for (int i2 = 0; i2 < 3; i2++)
#pragma unroll
        for (int j2 = 0; j2 < 3; j2++) {
            float wv = wr[i2 * 3 + j2];
            ox += r4[i2][j2]     * wv;
            oy += r4[i2][j2 + 1] * wv;
            oz += r4[i2 + 1][j2] * wv;
            ow += r4[i2 + 1][j2 + 1] * wv;
        }
    return make_float4(ox, oy, oz, ow);
}

// grid (16, 16, B*NHEADS), 256 threads. Each thread: 2x2 pixel quad, 4 channels in flight.
// smem: halo[8*360] + qs[24*QP2] + ks[24*QP2] = 61440 B  -> 3 CTAs/SM
__global__ __launch_bounds__(256) void dw_reduce_kernel(
    const float* __restrict__ pre_q, const float* __restrict__ pre_kv,
    const float* __restrict__ wq_dw, const float* __restrict__ wkv_dw,
    float* __restrict__ vout, float* __restrict__ ssq, float* __restrict__ ssk,
    float* __restrict__ gram)
{
    extern __shared__ float sm[];
    float* halo = sm;                  // 2880 floats
    float* qs   = sm + 2880;           // 24*QP2, channel-major, quad-major pixel index
    float* ks   = qs + 24 * QP2;

    const int tid = threadIdx.x;
    const int b   = blockIdx.z >> 3;
    const int h   = blockIdx.z & 7;
    const int cb  = h * CH;
    const int tx0 = blockIdx.x * 16;
    const int ty0 = blockIdx.y * 16;

    const int cs = tid >> 6;           // channel slot 0..3
    const int qd = tid & 63;           // quad index
    const int qy = qd >> 3, qx = qd & 7;
    const int hoff = (2 * qy) * 20 + 2 * qx;

    const float* srcq  = pre_q  + (size_t)b * CDIM * HWSZ;
    const float* srckv = pre_kv + (size_t)b * 2 * CDIM * HWSZ;

    // ---- q channels -> qs ----
#pragma unroll 1
    for (int g = 0; g < 3; g++) {
        load_halo8v(halo, srcq, cb + g * 8, ty0, tx0, tid);
        __syncthreads();
#pragma unroll
        for (int it = 0; it < 2; it++) {
            int cc = cs + it * 4;
            int c  = g * 8 + cc;
            const float* w = wq_dw + (size_t)(cb + c) * 9;
            float wr[9];
#pragma unroll
            for (int j = 0; j < 9; j++) wr[j] = __ldg(w + j);
            float4 o = dw_quad(halo + cc * 360 + hoff, wr);
            *reinterpret_cast<float4*>(qs + c * QP2 + qd * 4) = o;
        }
        __syncthreads();
    }
    // ---- k channels -> ks ----
#pragma unroll 1
    for (int g = 0; g < 3; g++) {
        load_halo8v(halo, srckv, cb + g * 8, ty0, tx0, tid);
        __syncthreads();
#pragma unroll
        for (int it = 0; it < 2; it++) {
            int cc = cs + it * 4;
            int c  = g * 8 + cc;
            const float* w = wkv_dw + (size_t)(cb + c) * 9;
            float wr[9];
#pragma unroll
            for (int j = 0; j < 9; j++) wr[j] = __ldg(w + j);
            float4 o = dw_quad(halo + cc * 360 + hoff, wr);
            *reinterpret_cast<float4*>(ks + c * QP2 + qd * 4) = o;
        }
        __syncthreads();
    }

    // ---- sum of squares: 24 channels x 8 slices, float4, shfl-reduced ----
    if (tid < 192) {
        int c = tid >> 3, s = tid & 7;
        float sq = 0.f, sk = 0.f;
#pragma unroll
        for (int i = 0; i < 8; i++) {
            int j = s + (i << 3);
            float4 a = *reinterpret_cast<const float4*>(qs + c * QP2 + 4 * j);
            sq += a.x * a.x + a.y * a.y + a.z * a.z + a.w * a.w;
            float4 kk = *reinterpret_cast<const float4*>(ks + c * QP2 + 4 * j);
            sk += kk.x * kk.x + kk.y * kk.y + kk.z * kk.z + kk.w * kk.w;
        }
#pragma unroll
        for (int off = 1; off < 8; off <<= 1) {
            sq += __shfl_xor_sync(0xffffffffu, sq, off);
            sk += __shfl_xor_sync(0xffffffffu, sk, off);
        }
        if (s == 0) {
            atomicAdd(&ssq[b * CDIM + cb + c], sq);
            atomicAdd(&ssk[b * CDIM + cb + c], sk);
        }
    }

    // ---- Gram: 36 tasks of 4x4 entries x 8 slices, float4 pixels, shfl-reduced ----
#pragma unroll 1
    for (int t = tid; t < 288; t += 256) {
        int e = t >> 3, s = t & 7;
        int c0 = (e / 6) * 4, d0 = (e % 6) * 4;
        float acc[16];
#pragma unroll
        for (int j = 0; j < 16; j++) acc[j] = 0.f;
#pragma unroll 2
        for (int i = 0; i < 8; i++) {
            int j = s + (i << 3);
            float4 qv[4], kv[4];
#pragma unroll
            for (int r = 0; r < 4; r++) {
                qv[r] = *reinterpret_cast<const float4*>(qs + (c0 + r) * QP2 + 4 * j);
                kv[r] = *reinterpret_cast<const float4*>(ks + (d0 + r) * QP2 + 4 * j);
            }
#pragma unroll
            for (int a = 0; a < 4; a++)
#pragma unroll
                for (int d = 0; d < 4; d++)
                    acc[a * 4 + d] += qv[a].x * kv[d].x + qv[a].y * kv[d].y
                                    + qv[a].z * kv[d].z + qv[a].w * kv[d].w;
        }
#pragma unroll
        for (int off = 1; off < 8; off <<= 1)
#pragma unroll
            for (int j = 0; j < 16; j++)
                acc[j] += __shfl_xor_sync(0xffffffffu, acc[j], off);
        if (s == 0) {
            float* gb = gram + (((size_t)b * NHEADS + h) * CH + c0) * CH + d0;
#pragma unroll
            for (int jq = 0; jq < 4; jq++)
#pragma unroll
                for (int jk = 0; jk < 4; jk++)
                    atomicAdd(&gb[jq * CH + jk], acc[jq * 4 + jk]);
        }
    }

    // ---- v channels -> global (float2 rows) ----
#pragma unroll 1
    for (int g = 0; g < 3; g++) {
        load_halo8v(halo, srckv, CDIM + cb + g * 8, ty0, tx0, tid);
        __syncthreads();
#pragma unroll
        for (int it = 0; it < 2; it++) {
            int cc = cs + it * 4;
            int c  = g * 8 + cc;
            const float* w = wkv_dw + (size_t)(CDIM + cb + c) * 9;
            float wr[9];
#pragma unroll
            for (int j = 0; j < 9; j++) wr[j] = __ldg(w + j);
            float4 o = dw_quad(halo + cc * 360 + hoff, wr);
            float* dst = vout + ((size_t)b * CDIM + cb + c) * HWSZ
                       + (ty0 + 2 * qy) * 256 + (tx0 + 2 * qx);
            *reinterpret_cast<float2*>(dst)       = make_float2(o.x, o.y);
            *reinterpret_cast<float2*>(dst + 256) = make_float2(o.z, o.w);
        }
        __syncthreads();
    }
}

// ---------------- softmax + M = Wproj * blockdiag(attn) ----------------
__global__ __launch_bounds__(256) void attn_proj_kernel(
    const float* __restrict__ gram, const float* __restrict__ ssq,
    const float* __restrict__ ssk,  const float* __restrict__ temp,
    const float* __restrict__ wproj, float* __restrict__ Mout)
{
    __shared__ float at[192][25];
    __shared__ float nk_s[192];
    const int b = blockIdx.x, tid = threadIdx.x;

    if (tid < 192) nk_s[tid] = fmaxf(sqrtf(ssk[b * CDIM + tid]), 1e-12f);
    __syncthreads();

    if (tid < 192) {
        int h = tid / 24, c = tid % 24;
        float nq = fmaxf(sqrtf(ssq[b * CDIM + tid]), 1e-12f);
        float tv = temp[h];
        const float* gr = gram + (((size_t)b * NHEADS + h) * CH + c) * CH;
        float vals[24];
        float mx = -1e30f;
#pragma unroll
        for (int d = 0; d < 24; d++) {
            float v = gr[d] / (nq * nk_s[h * 24 + d]) * tv;
            vals[d] = v;
            mx = fmaxf(mx, v);
        }
        float s = 0.f;
#pragma unroll
        for (int d = 0; d < 24; d++) { vals[d] = expf(vals[d] - mx); s += vals[d]; }
        float inv = 1.f / s;
#pragma unroll
        for (int d = 0; d < 24; d++) at[tid][d] = vals[d] * inv;
    }
    __syncthreads();

    for (int idx = tid; idx < 192 * 192; idx += 256) {
        int o = idx / 192, dg = idx % 192;
        int h = dg / 24, d = dg % 24;
        float s = 0.f;
#pragma unroll
        for (int c = 0; c < 24; c++)
            s += wproj[o * 192 + h * 24 + c] * at[h * 24 + c][d];
        Mout[(size_t)b * CDIM * CDIM + idx] = s;
    }
}

// ---------------- launch ----------------
extern "C" void kernel_launch(void* const* d_in, const int* in_sizes, int n_in,
                              void* d_out, int out_size) {
    const float* x      = (const float*)d_in[0];
    const float* x_ref  = (const float*)d_in[1];
    const float* wq     = (const float*)d_in[2];
    const float* wq_dw  = (const float*)d_in[3];
    const float* wkv    = (const float*)d_in[4];
    const float* wkv_dw = (const float*)d_in[5];
    const float* wproj  = (const float*)d_in[6];
    const float* temp   = (const float*)d_in[7];
    float* out = (float*)d_out;

    float *pre_q, *pre_kv, *vbuf, *gram, *ssq, *ssk, *Mm;
    cudaGetSymbolAddress((void**)&pre_q,  g_pre_q);
    cudaGetSymbolAddress((void**)&pre_kv, g_pre_kv);
    cudaGetSymbolAddress((void**)&vbuf,   g_v);
    cudaGetSymbolAddress((void**)&gram,   g_gram);
    cudaGetSymbolAddress((void**)&ssq,    g_ssq);
    cudaGetSymbolAddress((void**)&ssk,    g_ssk);
    cudaGetSymbolAddress((void**)&Mm,     g_M);

    const int smem2 = (2880 + 2 * 24 * QP2) * (int)sizeof(float);  // 61440 B
    cudaFuncSetAttribute(dw_reduce_kernel,
                         cudaFuncAttributeMaxDynamicSharedMemorySize, smem2);

    zero_stats_kernel<<<36, 256>>>(gram, ssq, ssk);

    gemm192_kernel<<<dim3(3, 512, BSZ), 256>>>(
        wq, 0LL, x, (long long)CDIM * HWSZ, pre_q, (long long)CDIM * HWSZ);
    gemm192_kernel<<<dim3(6, 512, BSZ), 256>>>(
        wkv, 0LL, x_ref, (long long)CDIM * HWSZ, pre_kv, (long long)2 * CDIM * HWSZ);

    dw_reduce_kernel<<<dim3(16, 16, BSZ * NHEADS), 256, smem2>>>(
        pre_q, pre_kv, wq_dw, wkv_dw, vbuf, ssq, ssk, gram);

    attn_proj_kernel<<<BSZ, 256>>>(gram, ssq, ssk, temp, wproj, Mm);

    gemm192_kernel<<<dim3(3, 512, BSZ), 256>>>(
        Mm, (long long)CDIM * CDIM, vbuf, (long long)CDIM * HWSZ,
        out, (long long)CDIM * HWSZ);
}

// round 4
// speedup vs baseline: 1.5233x; 1.0056x over previous
#include <cuda_runtime.h>

#define HWSZ  65536
#define CDIM  192
#define NHEADS 8
#define CH    24
#define BSZ   2
#define QP2   260   // qs/ks pixel stride (multiple of 4 for float4)

// ---------------- scratch (no cudaMalloc allowed) ----------------
__device__ float g_pre_q [(size_t)BSZ * CDIM     * HWSZ];   // 100.7 MB
__device__ float g_pre_kv[(size_t)BSZ * 2 * CDIM * HWSZ];   // 201.3 MB
__device__ float g_v    [(size_t)BSZ * CDIM      * HWSZ];   // 100.7 MB
__device__ float g_gram [BSZ * NHEADS * CH * CH];
__device__ float g_ssq  [BSZ * CDIM];
__device__ float g_ssk  [BSZ * CDIM];
__device__ float g_M    [BSZ * CDIM * CDIM];

// ---------------- f32x2 helpers (Blackwell packed fp32) ----------------
__device__ __forceinline__ unsigned long long pack2(float a, float b) {
    unsigned long long r;
    asm("mov.b64 %0, {%1, %2};" : "=l"(r) : "f"(a), "f"(b));
    return r;
}
__device__ __forceinline__ void fma2(unsigned long long& d,
                                     unsigned long long a, unsigned long long b) {
    asm("fma.rn.f32x2 %0, %1, %2, %3;" : "=l"(d) : "l"(a), "l"(b), "l"(d));
}
__device__ __forceinline__ float2 unpack2(unsigned long long v) {
    float2 f;
    asm("mov.b64 {%0, %1}, %2;" : "=f"(f.x), "=f"(f.y) : "l"(v));
    return f;
}

// ---------------- zero accumulators ----------------
__global__ void zero_stats_kernel(float* gram, float* ssq, float* ssk) {
    int i = blockIdx.x * 256 + threadIdx.x;
    if (i < BSZ * NHEADS * CH * CH) gram[i] = 0.f;
    if (i < BSZ * CDIM) { ssq[i] = 0.f; ssk[i] = 0.f; }
}

// ---------------- GEMM: Y[b][m][n] = sum_k W[b][m][k] * X[b][k][n] ----------------
__global__ __launch_bounds__(256) void gemm192_kernel(
    const float* __restrict__ Wm, long long wstride_b,
    const float* __restrict__ X,  long long xstride_b,
    float* __restrict__ Y,        long long ystride_b)
{
    __shared__ float As[16][72];
    __shared__ float Bs[16][128];

    const int tid = threadIdx.x;
    const int tx = tid & 15, ty = tid >> 4;
    const int m0 = blockIdx.x * 64;
    const int n0 = blockIdx.y * 128;
    const int b  = blockIdx.z;

    const float* Wb = Wm + (size_t)b * wstride_b;
    const float* Xb = X  + (size_t)b * xstride_b;
    float*       Yb = Y  + (size_t)b * ystride_b;

    const int ar = tid >> 2;
    const int ac = (tid & 3) << 2;

    unsigned long long acc[4][4];
#pragma unroll
    for (int i = 0; i < 4; i++)
#pragma unroll
        for (int j = 0; j < 4; j++) acc[i][j] = 0ull;

    for (int k0 = 0; k0 < 192; k0 += 16) {
        float4 a4 = *reinterpret_cast<const float4*>(Wb + (size_t)(m0 + ar) * 192 + k0 + ac);
        As[ac + 0][ar] = a4.x; As[ac + 1][ar] = a4.y;
        As[ac + 2][ar] = a4.z; As[ac + 3][ar] = a4.w;
#pragma unroll
        for (int i = 0; i < 2; i++) {
            int e  = tid + i * 256;
            int br = e >> 5;
            int bc = (e & 31) << 2;
            *reinterpret_cast<float4*>(&Bs[br][bc]) =
                *reinterpret_cast<const float4*>(Xb + (size_t)(k0 + br) * HWSZ + n0 + bc);
        }
        __syncthreads();
#pragma unroll
        for (int kk = 0; kk < 16; kk++) {
            float4 av = *reinterpret_cast<const float4*>(&As[kk][ty << 2]);
            unsigned long long aa[4];
            aa[0] = pack2(av.x, av.x); aa[1] = pack2(av.y, av.y);
            aa[2] = pack2(av.z, av.z); aa[3] = pack2(av.w, av.w);
            ulonglong2 bL = *reinterpret_cast<const ulonglong2*>(&Bs[kk][tx << 2]);
            ulonglong2 bH = *reinterpret_cast<const ulonglong2*>(&Bs[kk][64 + (tx << 2)]);
#pragma unroll
            for (int i = 0; i < 4; i++) {
                fma2(acc[i][0], aa[i], bL.x);
                fma2(acc[i][1], aa[i], bL.y);
                fma2(acc[i][2], aa[i], bH.x);
                fma2(acc[i][3], aa[i], bH.y);
            }
        }
        __syncthreads();
    }

#pragma unroll
    for (int i = 0; i < 4; i++) {
        size_t yb = (size_t)(m0 + (ty << 2) + i) * HWSZ + n0 + (tx << 2);
        float2 f0 = unpack2(acc[i][0]), f1 = unpack2(acc[i][1]);
        *reinterpret_cast<float4*>(Yb + yb) = make_float4(f0.x, f0.y, f1.x, f1.y);
        f0 = unpack2(acc[i][2]); f1 = unpack2(acc[i][3]);
        *reinterpret_cast<float4*>(Yb + yb + 64) = make_float4(f0.x, f0.y, f1.x, f1.y);
    }
}

// ---------------- dwconv3x3 + Gram + norms + v (head-parallel, vectorized) ----------------
// halo layout: 8 channels x 18 rows x stride 20 (col c holds gx = tx0-1+c)
__device__ __forceinline__ void load_halo8v(float* halo, const float* __restrict__ src,
                                            int chBase, int ty0, int tx0, int tid) {
    for (int i = tid; i < 8 * 324; i += 256) {
        int ch  = i / 324;
        int rem = i - ch * 324;
        int r   = rem / 18;
        int cc  = rem - r * 18;
        int gy = ty0 - 1 + r, gx = tx0 - 1 + cc;
        float vv = 0.f;
        if ((unsigned)gy < 256u && (unsigned)gx < 256u)
            vv = src[(size_t)(chBase + ch) * HWSZ + gy * 256 + gx];
        halo[ch * 360 + r * 20 + cc] = vv;
    }
}

// Compute 2x2 quad of dwconv outputs from a 4x4 tap region fetched as 8 x float2.
__device__ __forceinline__ float4 dw_quad(const float* hb, const float* wr) {
    float r4[4][4];
#pragma unroll
    for (int r = 0; r < 4; r++) {
        float2 a  = *reinterpret_cast<const float2*>(hb + r * 20);
        float2 b2 = *reinterpret_cast<const float2*>(hb + r * 20 + 2);
        r4[r][0] = a.x; r4[r][1] = a.y; r4[r][2] = b2.x; r4[r][3] = b2.y;
    }
    float ox = 0.f, oy = 0.f, oz = 0.f, ow = 0.f;
#pragma unroll
    for (int i2 = 0; i2 < 3; i2++)
#pragma unroll
        for (int j2 = 0; j2 < 3; j2++) {
            float wv = wr[i2 * 3 + j2];
            ox += r4[i2][j2]     * wv;
            oy += r4[i2][j2 + 1] * wv;
            oz += r4[i2 + 1][j2] * wv;
            ow += r4[i2 + 1][j2 + 1] * wv;
        }
    return make_float4(ox, oy, oz, ow);
}

// grid (16, 16, B*NHEADS), 256 threads. Each thread: 2x2 pixel quad, 4 channels in flight.
// smem: halo[8*360] + qs[24*QP2] + ks[24*QP2] = 61440 B  -> 3 CTAs/SM
__global__ __launch_bounds__(256) void dw_reduce_kernel(
    const float* __restrict__ pre_q, const float* __restrict__ pre_kv,
    const float* __restrict__ wq_dw, const float* __restrict__ wkv_dw,
    float* __restrict__ vout, float* __restrict__ ssq, float* __restrict__ ssk,
    float* __restrict__ gram)
{
    extern __shared__ float sm[];
    float* halo = sm;                  // 2880 floats
    float* qs   = sm + 2880;           // 24*QP2, channel-major, quad-major pixel index
    float* ks   = qs + 24 * QP2;

    const int tid = threadIdx.x;
    const int b   = blockIdx.z >> 3;
    const int h   = blockIdx.z & 7;
    const int cb  = h * CH;
    const int tx0 = blockIdx.x * 16;
    const int ty0 = blockIdx.y * 16;

    const int cs = tid >> 6;           // channel slot 0..3
    const int qd = tid & 63;           // quad index
    const int qy = qd >> 3, qx = qd & 7;
    const int hoff = (2 * qy) * 20 + 2 * qx;

    const float* srcq  = pre_q  + (size_t)b * CDIM * HWSZ;
    const float* srckv = pre_kv + (size_t)b * 2 * CDIM * HWSZ;

    // ---- q channels -> qs ----
#pragma unroll 1
    for (int g = 0; g < 3; g++) {
        load_halo8v(halo, srcq, cb + g * 8, ty0, tx0, tid);
        __syncthreads();
#pragma unroll
        for (int it = 0; it < 2; it++) {
            int cc = cs + it * 4;
            int c  = g * 8 + cc;
            const float* w = wq_dw + (size_t)(cb + c) * 9;
            float wr[9];
#pragma unroll
            for (int j = 0; j < 9; j++) wr[j] = __ldg(w + j);
            float4 o = dw_quad(halo + cc * 360 + hoff, wr);
            *reinterpret_cast<float4*>(qs + c * QP2 + qd * 4) = o;
        }
        __syncthreads();
    }
    // ---- k channels -> ks ----
#pragma unroll 1
    for (int g = 0; g < 3; g++) {
        load_halo8v(halo, srckv, cb + g * 8, ty0, tx0, tid);
        __syncthreads();
#pragma unroll
        for (int it = 0; it < 2; it++) {
            int cc = cs + it * 4;
            int c  = g * 8 + cc;
            const float* w = wkv_dw + (size_t)(cb + c) * 9;
            float wr[9];
#pragma unroll
            for (int j = 0; j < 9; j++) wr[j] = __ldg(w + j);
            float4 o = dw_quad(halo + cc * 360 + hoff, wr);
            *reinterpret_cast<float4*>(ks + c * QP2 + qd * 4) = o;
        }
        __syncthreads();
    }

    // ---- sum of squares: 24 channels x 8 slices, float4, shfl-reduced ----
    if (tid < 192) {
        int c = tid >> 3, s = tid & 7;
        float sq = 0.f, sk = 0.f;
#pragma unroll
        for (int i = 0; i < 8; i++) {
            int j = s + (i << 3);
            float4 a = *reinterpret_cast<const float4*>(qs + c * QP2 + 4 * j);
            sq += a.x * a.x + a.y * a.y + a.z * a.z + a.w * a.w;
            float4 kk = *reinterpret_cast<const float4*>(ks + c * QP2 + 4 * j);
            sk += kk.x * kk.x + kk.y * kk.y + kk.z * kk.z + kk.w * kk.w;
        }
#pragma unroll
        for (int off = 1; off < 8; off <<= 1) {
            sq += __shfl_xor_sync(0xffffffffu, sq, off);
            sk += __shfl_xor_sync(0xffffffffu, sk, off);
        }
        if (s == 0) {
            atomicAdd(&ssq[b * CDIM + cb + c], sq);
            atomicAdd(&ssk[b * CDIM + cb + c], sk);
        }
    }

    // ---- Gram: 36 tasks of 4x4 entries x 8 slices, float4 pixels, shfl-reduced ----
#pragma unroll 1
    for (int t = tid; t < 288; t += 256) {
        int e = t >> 3, s = t & 7;
        int c0 = (e / 6) * 4, d0 = (e % 6) * 4;
        float acc[16];
#pragma unroll
        for (int j = 0; j < 16; j++) acc[j] = 0.f;
#pragma unroll 2
        for (int i = 0; i < 8; i++) {
            int j = s + (i << 3);
            float4 qv[4], kv[4];
#pragma unroll
            for (int r = 0; r < 4; r++) {
                qv[r] = *reinterpret_cast<const float4*>(qs + (c0 + r) * QP2 + 4 * j);
                kv[r] = *reinterpret_cast<const float4*>(ks + (d0 + r) * QP2 + 4 * j);
            }
#pragma unroll
            for (int a = 0; a < 4; a++)
#pragma unroll
                for (int d = 0; d < 4; d++)
                    acc[a * 4 + d] += qv[a].x * kv[d].x + qv[a].y * kv[d].y
                                    + qv[a].z * kv[d].z + qv[a].w * kv[d].w;
        }
#pragma unroll
        for (int off = 1; off < 8; off <<= 1)
#pragma unroll
            for (int j = 0; j < 16; j++)
                acc[j] += __shfl_xor_sync(0xffffffffu, acc[j], off);
        if (s == 0) {
            float* gb = gram + (((size_t)b * NHEADS + h) * CH + c0) * CH + d0;
#pragma unroll
            for (int jq = 0; jq < 4; jq++)
#pragma unroll
                for (int jk = 0; jk < 4; jk++)
                    atomicAdd(&gb[jq * CH + jk], acc[jq * 4 + jk]);
        }
    }

    // ---- v channels -> global (float2 rows) ----
#pragma unroll 1
    for (int g = 0; g < 3; g++) {
        load_halo8v(halo, srckv, CDIM + cb + g * 8, ty0, tx0, tid);
        __syncthreads();
#pragma unroll
        for (int it = 0; it < 2; it++) {
            int cc = cs + it * 4;
            int c  = g * 8 + cc;
            const float* w = wkv_dw + (size_t)(CDIM + cb + c) * 9;
            float wr[9];
#pragma unroll
            for (int j = 0; j < 9; j++) wr[j] = __ldg(w + j);
            float4 o = dw_quad(halo + cc * 360 + hoff, wr);
            float* dst = vout + ((size_t)b * CDIM + cb + c) * HWSZ
                       + (ty0 + 2 * qy) * 256 + (tx0 + 2 * qx);
            *reinterpret_cast<float2*>(dst)       = make_float2(o.x, o.y);
            *reinterpret_cast<float2*>(dst + 256) = make_float2(o.z, o.w);
        }
        __syncthreads();
    }
}

// ---------------- softmax + M = Wproj * blockdiag(attn) ----------------
__global__ __launch_bounds__(256) void attn_proj_kernel(
    const float* __restrict__ gram, const float* __restrict__ ssq,
    const float* __restrict__ ssk,  const float* __restrict__ temp,
    const float* __restrict__ wproj, float* __restrict__ Mout)
{
    __shared__ float at[192][25];
    __shared__ float nk_s[192];
    const int b = blockIdx.x, tid = threadIdx.x;

    if (tid < 192) nk_s[tid] = fmaxf(sqrtf(ssk[b * CDIM + tid]), 1e-12f);
    __syncthreads();

    if (tid < 192) {
        int h = tid / 24, c = tid % 24;
        float nq = fmaxf(sqrtf(ssq[b * CDIM + tid]), 1e-12f);
        float tv = temp[h];
        const float* gr = gram + (((size_t)b * NHEADS + h) * CH + c) * CH;
        float vals[24];
        float mx = -1e30f;
#pragma unroll
        for (int d = 0; d < 24; d++) {
            float v = gr[d] / (nq * nk_s[h * 24 + d]) * tv;
            vals[d] = v;
            mx = fmaxf(mx, v);
        }
        float s = 0.f;
#pragma unroll
        for (int d = 0; d < 24; d++) { vals[d] = expf(vals[d] - mx); s += vals[d]; }
        float inv = 1.f / s;
#pragma unroll
        for (int d = 0; d < 24; d++) at[tid][d] = vals[d] * inv;
    }
    __syncthreads();

    for (int idx = tid; idx < 192 * 192; idx += 256) {
        int o = idx / 192, dg = idx % 192;
        int h = dg / 24, d = dg % 24;
        float s = 0.f;
#pragma unroll
        for (int c = 0; c < 24; c++)
            s += wproj[o * 192 + h * 24 + c] * at[h * 24 + c][d];
        Mout[(size_t)b * CDIM * CDIM + idx] = s;
    }
}

// ---------------- launch ----------------
extern "C" void kernel_launch(void* const* d_in, const int* in_sizes, int n_in,
                              void* d_out, int out_size) {
    const float* x      = (const float*)d_in[0];
    const float* x_ref  = (const float*)d_in[1];
    const float* wq     = (const float*)d_in[2];
    const float* wq_dw  = (const float*)d_in[3];
    const float* wkv    = (const float*)d_in[4];
    const float* wkv_dw = (const float*)d_in[5];
    const float* wproj  = (const float*)d_in[6];
    const float* temp   = (const float*)d_in[7];
    float* out = (float*)d_out;

    float *pre_q, *pre_kv, *vbuf, *gram, *ssq, *ssk, *Mm;
    cudaGetSymbolAddress((void**)&pre_q,  g_pre_q);
    cudaGetSymbolAddress((void**)&pre_kv, g_pre_kv);
    cudaGetSymbolAddress((void**)&vbuf,   g_v);
    cudaGetSymbolAddress((void**)&gram,   g_gram);
    cudaGetSymbolAddress((void**)&ssq,    g_ssq);
    cudaGetSymbolAddress((void**)&ssk,    g_ssk);
    cudaGetSymbolAddress((void**)&Mm,     g_M);

    const int smem2 = (2880 + 2 * 24 * QP2) * (int)sizeof(float);  // 61440 B
    cudaFuncSetAttribute(dw_reduce_kernel,
                         cudaFuncAttributeMaxDynamicSharedMemorySize, smem2);

    zero_stats_kernel<<<36, 256>>>(gram, ssq, ssk);

    gemm192_kernel<<<dim3(3, 512, BSZ), 256>>>(
        wq, 0LL, x, (long long)CDIM * HWSZ, pre_q, (long long)CDIM * HWSZ);
    gemm192_kernel<<<dim3(6, 512, BSZ), 256>>>(
        wkv, 0LL, x_ref, (long long)CDIM * HWSZ, pre_kv, (long long)2 * CDIM * HWSZ);

    dw_reduce_kernel<<<dim3(16, 16, BSZ * NHEADS), 256, smem2>>>(
        pre_q, pre_kv, wq_dw, wkv_dw, vbuf, ssq, ssk, gram);

    attn_proj_kernel<<<BSZ, 256>>>(gram, ssq, ssk, temp, wproj, Mm);

    gemm192_kernel<<<dim3(3, 512, BSZ), 256>>>(
        Mm, (long long)CDIM * CDIM, vbuf, (long long)CDIM * HWSZ,
        out, (long long)CDIM * HWSZ);
}

// round 6
// speedup vs baseline: 2.0688x; 1.3581x over previous
#include <cuda_runtime.h>
#include <cuda_bf16.h>
#include <cstdint>

#define HWSZ  65536
#define CDIM  192
#define NHEADS 8
#define CH    24
#define BSZ   2
#define QP2   260

// ---------------- scratch (no cudaMalloc allowed) ----------------
__device__ float g_pre_q [(size_t)BSZ * CDIM     * HWSZ];
__device__ float g_pre_kv[(size_t)BSZ * 2 * CDIM * HWSZ];
__device__ float g_v    [(size_t)BSZ * CDIM      * HWSZ];
__device__ float g_gram [BSZ * NHEADS * CH * CH];
__device__ float g_ssq  [BSZ * CDIM];
__device__ float g_ssk  [BSZ * CDIM];
__device__ float g_M    [BSZ * CDIM * CDIM];

// bf16 hi/lo copies of the GEMM weight matrices (row-major [rows][192])
__device__ __nv_bfloat16 g_whq [CDIM * CDIM];
__device__ __nv_bfloat16 g_wlq [CDIM * CDIM];
__device__ __nv_bfloat16 g_whkv[2 * CDIM * CDIM];
__device__ __nv_bfloat16 g_wlkv[2 * CDIM * CDIM];
__device__ __nv_bfloat16 g_whm [BSZ * CDIM * CDIM];
__device__ __nv_bfloat16 g_wlm [BSZ * CDIM * CDIM];

__device__ __forceinline__ uint32_t smem_u32(const void* p) {
    uint32_t a;
    asm("{ .reg .u64 t; cvta.to.shared.u64 t, %1; cvt.u32.u64 %0, t; }" : "=r"(a) : "l"(p));
    return a;
}

// ---------------- zero accumulators ----------------
__global__ void zero_stats_kernel(float* gram, float* ssq, float* ssk) {
    int i = blockIdx.x * 256 + threadIdx.x;
    if (i < BSZ * NHEADS * CH * CH) gram[i] = 0.f;
    if (i < BSZ * CDIM) { ssq[i] = 0.f; ssk[i] = 0.f; }
}

// ---------------- prep: fp32 W -> bf16 hi/lo ----------------
__global__ void w2bf16_kernel(const float* __restrict__ W, long long wstride_b,
                              int total, __nv_bfloat16* __restrict__ hi,
                              __nv_bfloat16* __restrict__ lo, long long ostride_b) {
    int b = blockIdx.z;
    int i = blockIdx.x * 256 + threadIdx.x;
    if (i >= total) return;
    float x = W[(size_t)b * wstride_b + i];
    __nv_bfloat16 h = __float2bfloat16(x);
    __nv_bfloat16 l = __float2bfloat16(x - __bfloat162float(h));
    hi[(size_t)b * ostride_b + i] = h;
    lo[(size_t)b * ostride_b + i] = l;
}

// ---------------- HMMA bf16-split GEMM ----------------
// Y[nt*192 + m][p] = sum_k W[nt*192+m][k] * X[k][p],  K = 192.
// CTA tile: BM=192, BN=64, BK=16. 256 threads = 8 warps (4m x 2n), warp tile 48x32.
// 3 mma passes per fragment: Ahi*Bhi + Ahi*Blo + Alo*Bhi.
#define AST 24    // As row stride (bf16): 48B -> conflict-free ldmatrix
#define BST 72    // Bs row stride (bf16): 144B -> conflict-free ldmatrix
__global__ __launch_bounds__(256) void hmma_gemm_kernel(
    const float* __restrict__ X, long long xstride_b,
    const __nv_bfloat16* __restrict__ Whi, const __nv_bfloat16* __restrict__ Wlo,
    long long wstride_b,
    float* __restrict__ Y, long long ystride_b)
{
    __shared__ __nv_bfloat16 As_hi[192 * AST];
    __shared__ __nv_bfloat16 As_lo[192 * AST];
    __shared__ __nv_bfloat16 Bs_hi[16 * BST];
    __shared__ __nv_bfloat16 Bs_lo[16 * BST];

    const int tid = threadIdx.x;
    const int lid = tid & 31;
    const int wid = tid >> 5;
    const int wm  = wid >> 1;        // 0..3 -> m block of 48
    const int wn  = wid & 1;         // 0..1 -> n block of 32
    const int p0  = blockIdx.x * 64;
    const int nt  = blockIdx.y;
    const int b   = blockIdx.z;

    const float* Xb = X + (size_t)b * xstride_b + p0;
    const __nv_bfloat16* WhiB = Whi + (size_t)b * wstride_b + (size_t)nt * 192 * 192;
    const __nv_bfloat16* WloB = Wlo + (size_t)b * wstride_b + (size_t)nt * 192 * 192;

    float acc[3][4][4];
#pragma unroll
    for (int i = 0; i < 3; i++)
#pragma unroll
        for (int j = 0; j < 4; j++)
#pragma unroll
            for (int r = 0; r < 4; r++) acc[i][j][r] = 0.f;

    // ldmatrix lane addressing (precomputed element offsets)
    const int arow = (lid & 7) + ((lid >> 3) & 1) * 8;
    const int acol = (lid >> 4) * 8;
    const int brow = arow;
    const int bcoff = ((lid >> 4) & 1) * 8;

#pragma unroll 1
    for (int k0 = 0; k0 < 192; k0 += 16) {
        // ---- load W tile [192][16] hi/lo -> As (3 x uint2 per thread per tensor) ----
#pragma unroll
        for (int j = 0; j < 3; j++) {
            int idx = tid + j * 256;
            int row = idx >> 2, c4 = (idx & 3) << 2;
            size_t g = (size_t)row * 192 + k0 + c4;
            *reinterpret_cast<uint2*>(&As_hi[row * AST + c4]) =
                *reinterpret_cast<const uint2*>(WhiB + g);
            *reinterpret_cast<uint2*>(&As_lo[row * AST + c4]) =
                *reinterpret_cast<const uint2*>(WloB + g);
        }
        // ---- load X tile [16][64] fp32, convert -> Bs hi/lo ----
        {
            int row = tid >> 4, c4 = (tid & 15) << 2;
            float4 v = *reinterpret_cast<const float4*>(Xb + (size_t)(k0 + row) * HWSZ + c4);
            __nv_bfloat16 hx = __float2bfloat16(v.x), hy = __float2bfloat16(v.y);
            __nv_bfloat16 hz = __float2bfloat16(v.z), hw = __float2bfloat16(v.w);
            __nv_bfloat162 h01 = __nv_bfloat162(hx, hy), h23 = __nv_bfloat162(hz, hw);
            __nv_bfloat162 l01 = __nv_bfloat162(
                __float2bfloat16(v.x - __bfloat162float(hx)),
                __float2bfloat16(v.y - __bfloat162float(hy)));
            __nv_bfloat162 l23 = __nv_bfloat162(
                __float2bfloat16(v.z - __bfloat162float(hz)),
                __float2bfloat16(v.w - __bfloat162float(hw)));
            *reinterpret_cast<__nv_bfloat162*>(&Bs_hi[row * BST + c4])     = h01;
            *reinterpret_cast<__nv_bfloat162*>(&Bs_hi[row * BST + c4 + 2]) = h23;
            *reinterpret_cast<__nv_bfloat162*>(&Bs_lo[row * BST + c4])     = l01;
            *reinterpret_cast<__nv_bfloat162*>(&Bs_lo[row * BST + c4 + 2]) = l23;
        }
        __syncthreads();

        // ---- fragments ----
        uint32_t ah[3][4], al[3][4], bh[2][4], bl[2][4];
#pragma unroll
        for (int mi = 0; mi < 3; mi++) {
            int r = wm * 48 + mi * 16 + arow;
            uint32_t addr_h = smem_u32(&As_hi[r * AST + acol]);
            uint32_t addr_l = smem_u32(&As_lo[r * AST + acol]);
            asm volatile("ldmatrix.sync.aligned.m8n8.x4.shared.b16 {%0,%1,%2,%3}, [%4];"
                : "=r"(ah[mi][0]), "=r"(ah[mi][1]), "=r"(ah[mi][2]), "=r"(ah[mi][3]) : "r"(addr_h));
            asm volatile("ldmatrix.sync.aligned.m8n8.x4.shared.b16 {%0,%1,%2,%3}, [%4];"
                : "=r"(al[mi][0]), "=r"(al[mi][1]), "=r"(al[mi][2]), "=r"(al[mi][3]) : "r"(addr_l));
        }
#pragma unroll
        for (int blk = 0; blk < 2; blk++) {
            int col = wn * 32 + blk * 16 + bcoff;
            uint32_t addr_h = smem_u32(&Bs_hi[brow * BST + col]);
            uint32_t addr_l = smem_u32(&Bs_lo[brow * BST + col]);
            asm volatile("ldmatrix.sync.aligned.m8n8.x4.trans.shared.b16 {%0,%1,%2,%3}, [%4];"
                : "=r"(bh[blk][0]), "=r"(bh[blk][1]), "=r"(bh[blk][2]), "=r"(bh[blk][3]) : "r"(addr_h));
            asm volatile("ldmatrix.sync.aligned.m8n8.x4.trans.shared.b16 {%0,%1,%2,%3}, [%4];"
                : "=r"(bl[blk][0]), "=r"(bl[blk][1]), "=r"(bl[blk][2]), "=r"(bl[blk][3]) : "r"(addr_l));
        }

#define MMA(C, A, B0, B1) \
    asm volatile("mma.sync.aligned.m16n8k16.row.col.f32.bf16.bf16.f32 " \
        "{%0,%1,%2,%3}, {%4,%5,%6,%7}, {%8,%9}, {%0,%1,%2,%3};" \
        : "+f"((C)[0]), "+f"((C)[1]), "+f"((C)[2]), "+f"((C)[3]) \
        : "r"((A)[0]), "r"((A)[1]), "r"((A)[2]), "r"((A)[3]), "r"(B0), "r"(B1))

#pragma unroll
        for (int mi = 0; mi < 3; mi++)
#pragma unroll
            for (int ni = 0; ni < 4; ni++) {
                int blk = ni >> 1, half = (ni & 1) << 1;
                MMA(acc[mi][ni], ah[mi], bh[blk][half], bh[blk][half + 1]);
                MMA(acc[mi][ni], ah[mi], bl[blk][half], bl[blk][half + 1]);
                MMA(acc[mi][ni], al[mi], bh[blk][half], bh[blk][half + 1]);
            }
        __syncthreads();
    }

    // ---- epilogue: D frag m16n8 -> Y[row][pixel] ----
    float* Yb = Y + (size_t)b * ystride_b + (size_t)nt * 192 * HWSZ + p0;
#pragma unroll
    for (int mi = 0; mi < 3; mi++) {
        int r0 = wm * 48 + mi * 16 + (lid >> 2);
#pragma unroll
        for (int ni = 0; ni < 4; ni++) {
            int px = wn * 32 + ni * 8 + (lid & 3) * 2;
            *reinterpret_cast<float2*>(Yb + (size_t)r0 * HWSZ + px) =
                make_float2(acc[mi][ni][0], acc[mi][ni][1]);
            *reinterpret_cast<float2*>(Yb + (size_t)(r0 + 8) * HWSZ + px) =
                make_float2(acc[mi][ni][2], acc[mi][ni][3]);
        }
    }
}

// ---------------- dwconv3x3 + Gram + norms + v ----------------
__device__ __forceinline__ void load_halo8v(float* halo, const float* __restrict__ src,
                                            int chBase, int ty0, int tx0, int tid) {
    for (int i = tid; i < 8 * 324; i += 256) {
        int ch  = i / 324;
        int rem = i - ch * 324;
        int r   = rem / 18;
        int cc  = rem - r * 18;
        int gy = ty0 - 1 + r, gx = tx0 - 1 + cc;
        float vv = 0.f;
        if ((unsigned)gy < 256u && (unsigned)gx < 256u)
            vv = src[(size_t)(chBase + ch) * HWSZ + gy * 256 + gx];
        halo[ch * 360 + r * 20 + cc] = vv;
    }
}

__device__ __forceinline__ float4 dw_quad(const float* hb, const float* wr) {
    float r4[4][4];
#pragma unroll
    for (int r = 0; r < 4; r++) {
        float2 a  = *reinterpret_cast<const float2*>(hb + r * 20);
        float2 b2 = *reinterpret_cast<const float2*>(hb + r * 20 + 2);
        r4[r][0] = a.x; r4[r][1] = a.y; r4[r][2] = b2.x; r4[r][3] = b2.y;
    }
    float ox = 0.f, oy = 0.f, oz = 0.f, ow = 0.f;
#pragma unroll
    for (int i2 = 0; i2 < 3; i2++)
#pragma unroll
        for (int j2 = 0; j2 < 3; j2++) {
            float wv = wr[i2 * 3 + j2];
            ox += r4[i2][j2]     * wv;
            oy += r4[i2][j2 + 1] * wv;
            oz += r4[i2 + 1][j2] * wv;
            ow += r4[i2 + 1][j2 + 1] * wv;
        }
    return make_float4(ox, oy, oz, ow);
}

__global__ __launch_bounds__(256) void dw_reduce_kernel(
    const float* __restrict__ pre_q, const float* __restrict__ pre_kv,
    const float* __restrict__ wq_dw, const float* __restrict__ wkv_dw,
    float* __restrict__ vout, float* __restrict__ ssq, float* __restrict__ ssk,
    float* __restrict__ gram)
{
    extern __shared__ float sm[];
    float* halo = sm;
    float* qs   = sm + 2880;
    float* ks   = qs + 24 * QP2;

    const int tid = threadIdx.x;
    const int b   = blockIdx.z >> 3;
    const int h   = blockIdx.z & 7;
    const int cb  = h * CH;
    const int tx0 = blockIdx.x * 16;
    const int ty0 = blockIdx.y * 16;

    const int cs = tid >> 6;
    const int qd = tid & 63;
    const int qy = qd >> 3, qx = qd & 7;
    const int hoff = (2 * qy) * 20 + 2 * qx;

    const float* srcq  = pre_q  + (size_t)b * CDIM * HWSZ;
    const float* srckv = pre_kv + (size_t)b * 2 * CDIM * HWSZ;

#pragma unroll 1
    for (int g = 0; g < 3; g++) {
        load_halo8v(halo, srcq, cb + g * 8, ty0, tx0, tid);
        __syncthreads();
#pragma unroll
        for (int it = 0; it < 2; it++) {
            int cc = cs + it * 4;
            int c  = g * 8 + cc;
            const float* w = wq_dw + (size_t)(cb + c) * 9;
            float wr[9];
#pragma unroll
            for (int j = 0; j < 9; j++) wr[j] = __ldg(w + j);
            float4 o = dw_quad(halo + cc * 360 + hoff, wr);
            *reinterpret_cast<float4*>(qs + c * QP2 + qd * 4) = o;
        }
        __syncthreads();
    }
#pragma unroll 1
    for (int g = 0; g < 3; g++) {
        load_halo8v(halo, srckv, cb + g * 8, ty0, tx0, tid);
        __syncthreads();
#pragma unroll
        for (int it = 0; it < 2; it++) {
            int cc = cs + it * 4;
            int c  = g * 8 + cc;
            const float* w = wkv_dw + (size_t)(cb + c) * 9;
            float wr[9];
#pragma unroll
            for (int j = 0; j < 9; j++) wr[j] = __ldg(w + j);
            float4 o = dw_quad(halo + cc * 360 + hoff, wr);
            *reinterpret_cast<float4*>(ks + c * QP2 + qd * 4) = o;
        }
        __syncthreads();
    }

    if (tid < 192) {
        int c = tid >> 3, s = tid & 7;
        float sq = 0.f, sk = 0.f;
#pragma unroll
        for (int i = 0; i < 8; i++) {
            int j = s + (i << 3);
            float4 a = *reinterpret_cast<const float4*>(qs + c * QP2 + 4 * j);
            sq += a.x * a.x + a.y * a.y + a.z * a.z + a.w * a.w;
            float4 kk = *reinterpret_cast<const float4*>(ks + c * QP2 + 4 * j);
            sk += kk.x * kk.x + kk.y * kk.y + kk.z * kk.z + kk.w * kk.w;
        }
#pragma unroll
        for (int off = 1; off < 8; off <<= 1) {
            sq += __shfl_xor_sync(0xffffffffu, sq, off);
            sk += __shfl_xor_sync(0xffffffffu, sk, off);
        }
        if (s == 0) {
            atomicAdd(&ssq[b * CDIM + cb + c], sq);
            atomicAdd(&ssk[b * CDIM + cb + c], sk);
        }
    }

#pragma unroll 1
    for (int t = tid; t < 288; t += 256) {
        int e = t >> 3, s = t & 7;
        int c0 = (e / 6) * 4, d0 = (e % 6) * 4;
        float acc[16];
#pragma unroll
        for (int j = 0; j < 16; j++) acc[j] = 0.f;
#pragma unroll 2
        for (int i = 0; i < 8; i++) {
            int j = s + (i << 3);
            float4 qv[4], kv[4];
#pragma unroll
            for (int r = 0; r < 4; r++) {
                qv[r] = *reinterpret_cast<const float4*>(qs + (c0 + r) * QP2 + 4 * j);
                kv[r] = *reinterpret_cast<const float4*>(ks + (d0 + r) * QP2 + 4 * j);
            }
#pragma unroll
            for (int a = 0; a < 4; a++)
#pragma unroll
                for (int d = 0; d < 4; d++)
                    acc[a * 4 + d] += qv[a].x * kv[d].x + qv[a].y * kv[d].y
                                    + qv[a].z * kv[d].z + qv[a].w * kv[d].w;
        }
#pragma unroll
        for (int off = 1; off < 8; off <<= 1)
#pragma unroll
            for (int j = 0; j < 16; j++)
                acc[j] += __shfl_xor_sync(0xffffffffu, acc[j], off);
        if (s == 0) {
            float* gb = gram + (((size_t)b * NHEADS + h) * CH + c0) * CH + d0;
#pragma unroll
            for (int jq = 0; jq < 4; jq++)
#pragma unroll
                for (int jk = 0; jk < 4; jk++)
                    atomicAdd(&gb[jq * CH + jk], acc[jq * 4 + jk]);
        }
    }

#pragma unroll 1
    for (int g = 0; g < 3; g++) {
        load_halo8v(halo, srckv, CDIM + cb + g * 8, ty0, tx0, tid);
        __syncthreads();
#pragma unroll
        for (int it = 0; it < 2; it++) {
            int cc = cs + it * 4;
            int c  = g * 8 + cc;
            const float* w = wkv_dw + (size_t)(CDIM + cb + c) * 9;
            float wr[9];
#pragma unroll
            for (int j = 0; j < 9; j++) wr[j] = __ldg(w + j);
            float4 o = dw_quad(halo + cc * 360 + hoff, wr);
            float* dst = vout + ((size_t)b * CDIM + cb + c) * HWSZ
                       + (ty0 + 2 * qy) * 256 + (tx0 + 2 * qx);
            *reinterpret_cast<float2*>(dst)       = make_float2(o.x, o.y);
            *reinterpret_cast<float2*>(dst + 256) = make_float2(o.z, o.w);
        }
        __syncthreads();
    }
}

// ---------------- softmax + M = Wproj * blockdiag(attn) ----------------
__global__ __launch_bounds__(256) void attn_proj_kernel(
    const float* __restrict__ gram, const float* __restrict__ ssq,
    const float* __restrict__ ssk,  const float* __restrict__ temp,
    const float* __restrict__ wproj, float* __restrict__ Mout)
{
    __shared__ float at[192][25];
    __shared__ float nk_s[192];
    const int b = blockIdx.x, tid = threadIdx.x;

    if (tid < 192) nk_s[tid] = fmaxf(sqrtf(ssk[b * CDIM + tid]), 1e-12f);
    __syncthreads();

    if (tid < 192) {
        int h = tid / 24, c = tid % 24;
        float nq = fmaxf(sqrtf(ssq[b * CDIM + tid]), 1e-12f);
        float tv = temp[h];
        const float* gr = gram + (((size_t)b * NHEADS + h) * CH + c) * CH;
        float vals[24];
        float mx = -1e30f;
#pragma unroll
        for (int d = 0; d < 24; d++) {
            float v = gr[d] / (nq * nk_s[h * 24 + d]) * tv;
            vals[d] = v;
            mx = fmaxf(mx, v);
        }
        float s = 0.f;
#pragma unroll
        for (int d = 0; d < 24; d++) { vals[d] = expf(vals[d] - mx); s += vals[d]; }
        float inv = 1.f / s;
#pragma unroll
        for (int d = 0; d < 24; d++) at[tid][d] = vals[d] * inv;
    }
    __syncthreads();

    for (int idx = tid; idx < 192 * 192; idx += 256) {
        int o = idx / 192, dg = idx % 192;
        int h = dg / 24, d = dg % 24;
        float s = 0.f;
#pragma unroll
        for (int c = 0; c < 24; c++)
            s += wproj[o * 192 + h * 24 + c] * at[h * 24 + c][d];
        Mout[(size_t)b * CDIM * CDIM + idx] = s;
    }
}

// ---------------- launch ----------------
extern "C" void kernel_launch(void* const* d_in, const int* in_sizes, int n_in,
                              void* d_out, int out_size) {
    const float* x      = (const float*)d_in[0];
    const float* x_ref  = (const float*)d_in[1];
    const float* wq     = (const float*)d_in[2];
    const float* wq_dw  = (const float*)d_in[3];
    const float* wkv    = (const float*)d_in[4];
    const float* wkv_dw = (const float*)d_in[5];
    const float* wproj  = (const float*)d_in[6];
    const float* temp   = (const float*)d_in[7];
    float* out = (float*)d_out;

    float *pre_q, *pre_kv, *vbuf, *gram, *ssq, *ssk, *Mm;
    __nv_bfloat16 *whq, *wlq, *whkv, *wlkv, *whm, *wlm;
    cudaGetSymbolAddress((void**)&pre_q,  g_pre_q);
    cudaGetSymbolAddress((void**)&pre_kv, g_pre_kv);
    cudaGetSymbolAddress((void**)&vbuf,   g_v);
    cudaGetSymbolAddress((void**)&gram,   g_gram);
    cudaGetSymbolAddress((void**)&ssq,    g_ssq);
    cudaGetSymbolAddress((void**)&ssk,    g_ssk);
    cudaGetSymbolAddress((void**)&Mm,     g_M);
    cudaGetSymbolAddress((void**)&whq,  g_whq);
    cudaGetSymbolAddress((void**)&wlq,  g_wlq);
    cudaGetSymbolAddress((void**)&whkv, g_whkv);
    cudaGetSymbolAddress((void**)&wlkv, g_wlkv);
    cudaGetSymbolAddress((void**)&whm,  g_whm);
    cudaGetSymbolAddress((void**)&wlm,  g_wlm);

    const int smem2 = (2880 + 2 * 24 * QP2) * (int)sizeof(float);
    cudaFuncSetAttribute(dw_reduce_kernel,
                         cudaFuncAttributeMaxDynamicSharedMemorySize, smem2);

    zero_stats_kernel<<<36, 256>>>(gram, ssq, ssk);

    // W -> bf16 hi/lo
    w2bf16_kernel<<<dim3(144, 1, 1), 256>>>(wq,  0LL, CDIM * CDIM, whq,  wlq,  0LL);
    w2bf16_kernel<<<dim3(288, 1, 1), 256>>>(wkv, 0LL, 2 * CDIM * CDIM, whkv, wlkv, 0LL);

    // pre_q = Wq @ x
    hmma_gemm_kernel<<<dim3(1024, 1, BSZ), 256>>>(
        x, (long long)CDIM * HWSZ, whq, wlq, 0LL,
        pre_q, (long long)CDIM * HWSZ);
    // pre_kv = Wkv @ x_ref
    hmma_gemm_kernel<<<dim3(1024, 2, BSZ), 256>>>(
        x_ref, (long long)CDIM * HWSZ, whkv, wlkv, 0LL,
        pre_kv, (long long)2 * CDIM * HWSZ);

    dw_reduce_kernel<<<dim3(16, 16, BSZ * NHEADS), 256, smem2>>>(
        pre_q, pre_kv, wq_dw, wkv_dw, vbuf, ssq, ssk, gram);

    attn_proj_kernel<<<BSZ, 256>>>(gram, ssq, ssk, temp, wproj, Mm);

    // M -> bf16 hi/lo, then out = M_b @ v
    w2bf16_kernel<<<dim3(144, 1, BSZ), 256>>>(Mm, (long long)CDIM * CDIM,
                                              CDIM * CDIM, whm, wlm,
                                              (long long)CDIM * CDIM);
    hmma_gemm_kernel<<<dim3(1024, 1, BSZ), 256>>>(
        vbuf, (long long)CDIM * HWSZ, whm, wlm, (long long)CDIM * CDIM,
        out, (long long)CDIM * HWSZ);
}

// round 9
// speedup vs baseline: 2.2415x; 1.0835x over previous
#include <cuda_runtime.h>
#include <cuda_bf16.h>
#include <cstdint>

#define HWSZ  65536
#define CDIM  192
#define NHEADS 8
#define CH    24
#define BSZ   2
#define QP2   260

// ---------------- scratch (no cudaMalloc allowed) ----------------
__device__ float g_pre_q [(size_t)BSZ * CDIM     * HWSZ];
__device__ float g_pre_kv[(size_t)BSZ * 2 * CDIM * HWSZ];
__device__ float g_v    [(size_t)BSZ * CDIM      * HWSZ];
__device__ float g_gram [BSZ * NHEADS * CH * CH];
__device__ float g_ssq  [BSZ * CDIM];
__device__ float g_ssk  [BSZ * CDIM];
__device__ float g_M    [BSZ * CDIM * CDIM];

// bf16 hi/lo copies of the GEMM weight matrices (row-major [rows][192])
__device__ __nv_bfloat16 g_whq [CDIM * CDIM];
__device__ __nv_bfloat16 g_wlq [CDIM * CDIM];
__device__ __nv_bfloat16 g_whkv[2 * CDIM * CDIM];
__device__ __nv_bfloat16 g_wlkv[2 * CDIM * CDIM];
__device__ __nv_bfloat16 g_whm [BSZ * CDIM * CDIM];
__device__ __nv_bfloat16 g_wlm [BSZ * CDIM * CDIM];

__device__ __forceinline__ uint32_t smem_u32(const void* p) {
    uint32_t a;
    asm("{ .reg .u64 t; cvta.to.shared.u64 t, %1; cvt.u32.u64 %0, t; }" : "=r"(a) : "l"(p));
    return a;
}
__device__ __forceinline__ void cpa16(uint32_t dst, const void* src) {
    asm volatile("cp.async.cg.shared.global [%0], [%1], 16;" :: "r"(dst), "l"(src));
}
#define CPA_COMMIT() asm volatile("cp.async.commit_group;" ::: "memory")
#define CPA_WAIT(n)  asm volatile("cp.async.wait_group %0;" :: "n"(n) : "memory")

// pack two fp32 -> bf16x2 word (lo half = a, hi half = b)
__device__ __forceinline__ uint32_t pack_bf16x2(float a, float b) {
    uint32_t r;
    asm("cvt.rn.bf16x2.f32 %0, %1, %2;" : "=r"(r) : "f"(b), "f"(a));
    return r;
}
// recover fp32 from bf16 bit pattern (lower/upper half of packed word)
__device__ __forceinline__ float bf16lo_f(uint32_t w) { return __uint_as_float(w << 16); }
__device__ __forceinline__ float bf16hi_f(uint32_t w) { return __uint_as_float(w & 0xFFFF0000u); }

// ---------------- zero accumulators ----------------
__global__ void zero_stats_kernel(float* gram, float* ssq, float* ssk) {
    int i = blockIdx.x * 256 + threadIdx.x;
    if (i < BSZ * NHEADS * CH * CH) gram[i] = 0.f;
    if (i < BSZ * CDIM) { ssq[i] = 0.f; ssk[i] = 0.f; }
}

// ---------------- prep: fp32 W -> bf16 hi/lo ----------------
__global__ void w2bf16_kernel(const float* __restrict__ W, long long wstride_b,
                              int total, __nv_bfloat16* __restrict__ hi,
                              __nv_bfloat16* __restrict__ lo, long long ostride_b) {
    int b = blockIdx.z;
    int i = blockIdx.x * 256 + threadIdx.x;
    if (i >= total) return;
    float x = W[(size_t)b * wstride_b + i];
    __nv_bfloat16 h = __float2bfloat16(x);
    __nv_bfloat16 l = __float2bfloat16(x - __bfloat162float(h));
    hi[(size_t)b * ostride_b + i] = h;
    lo[(size_t)b * ostride_b + i] = l;
}

// ---------------- pipelined HMMA bf16-split GEMM ----------------
// Y[nt*192 + m][p] = sum_k W[nt*192+m][k] * X[k][p],  K = 192.
// CTA tile BM=192, BN=64, BK=16; 8 warps (4m x 2n), warp tile 48x32.
// W: cp.async 3-stage; X: reg-prefetch + STS, 2-stage. 1 sync per k-step.
#define AST 24    // As row stride (bf16)
#define BST 72    // Bs row stride (bf16)
// dyn smem element offsets (bf16 units)
#define OFF_WH(s) ((s) * 4608)
#define OFF_WL(s) (13824 + (s) * 4608)
#define OFF_XH(s) (27648 + (s) * 1152)
#define OFF_XL(s) (29952 + (s) * 1152)
#define GEMM_SMEM (32256 * 2)

__global__ __launch_bounds__(256, 2) void hmma_gemm_kernel(
    const float* __restrict__ X, long long xstride_b,
    const __nv_bfloat16* __restrict__ Whi, const __nv_bfloat16* __restrict__ Wlo,
    long long wstride_b,
    float* __restrict__ Y, long long ystride_b)
{
    extern __shared__ __nv_bfloat16 sms[];
    const uint32_t sb = smem_u32(sms);

    const int tid = threadIdx.x;
    const int lid = tid & 31;
    const int wid = tid >> 5;
    const int wm  = wid >> 1;
    const int wn  = wid & 1;
    const int p0  = blockIdx.x * 64;
    const int nt  = blockIdx.y;
    const int b   = blockIdx.z;

    const float* Xb = X + (size_t)b * xstride_b + p0;
    const __nv_bfloat16* WhiB = Whi + (size_t)b * wstride_b + (size_t)nt * 192 * 192;
    const __nv_bfloat16* WloB = Wlo + (size_t)b * wstride_b + (size_t)nt * 192 * 192;

    float acc[3][4][4];
#pragma unroll
    for (int i = 0; i < 3; i++)
#pragma unroll
        for (int j = 0; j < 4; j++)
#pragma unroll
            for (int r = 0; r < 4; r++) acc[i][j][r] = 0.f;

    const int widx = tid;
    const int xrow = tid >> 4, xc4 = (tid & 15) << 2;

    // ldmatrix lane addressing
    const int arow = (lid & 7) + ((lid >> 3) & 1) * 8;
    const int acol = (lid >> 4) * 8;
    const int brow = arow;
    const int bcoff = ((lid >> 4) & 1) * 8;

    // ---- prologue: W stages 0,1 in flight; X(0) in regs ----
#pragma unroll
    for (int s = 0; s < 2; s++) {
#pragma unroll
        for (int j = 0; j < 3; j++) {
            int idx = widx + j * 256;
            int tensor = idx >= 384;
            int r2 = idx - (tensor ? 384 : 0);      // exact mod-384 (FIX: was idx & 383)
            int row = r2 >> 1;
            int c8 = (r2 & 1) << 3;
            const __nv_bfloat16* src =
                (tensor ? WloB : WhiB) + (size_t)row * 192 + s * 16 + c8;
            uint32_t dst = sb + (uint32_t)(((tensor ? OFF_WL(s) : OFF_WH(s))
                                            + row * AST + c8) * 2);
            cpa16(dst, src);
        }
        CPA_COMMIT();
    }
    float4 xv = *reinterpret_cast<const float4*>(Xb + (size_t)xrow * HWSZ + xc4);

#pragma unroll 1
    for (int it = 0; it < 12; it++) {
        const int ws = it % 3;          // W stage
        const int xs = it & 1;          // X stage

        // ---- STS X(it) from regs (convert to bf16 hi/lo, packed words) ----
        {
            uint32_t h01 = pack_bf16x2(xv.x, xv.y);
            uint32_t h23 = pack_bf16x2(xv.z, xv.w);
            uint32_t l01 = pack_bf16x2(xv.x - bf16lo_f(h01), xv.y - bf16hi_f(h01));
            uint32_t l23 = pack_bf16x2(xv.z - bf16lo_f(h23), xv.w - bf16hi_f(h23));
            uint32_t xh = sb + (uint32_t)((OFF_XH(xs) + xrow * BST + xc4) * 2);
            uint32_t xl = sb + (uint32_t)((OFF_XL(xs) + xrow * BST + xc4) * 2);
            asm volatile("st.shared.v2.u32 [%0], {%1, %2};" :: "r"(xh), "r"(h01), "r"(h23));
            asm volatile("st.shared.v2.u32 [%0], {%1, %2};" :: "r"(xl), "r"(l01), "r"(l23));
        }

        // ---- wait for W(it) (one newer group may stay in flight) ----
        if (it < 11) { CPA_WAIT(1); } else { CPA_WAIT(0); }
        __syncthreads();

        // ---- issue W(it+2) into stage (it+2)%3 ----
        if (it < 10) {
            int s = it + 2, ss = s % 3;
#pragma unroll
            for (int j = 0; j < 3; j++) {
                int idx = widx + j * 256;
                int tensor = idx >= 384;
                int r2 = idx - (tensor ? 384 : 0);  // exact mod-384 (FIX)
                int row = r2 >> 1;
                int c8 = (r2 & 1) << 3;
                const __nv_bfloat16* src =
                    (tensor ? WloB : WhiB) + (size_t)row * 192 + s * 16 + c8;
                uint32_t dst = sb + (uint32_t)(((tensor ? OFF_WL(ss) : OFF_WH(ss))
                                                + row * AST + c8) * 2);
                cpa16(dst, src);
            }
            CPA_COMMIT();
        }
        // ---- prefetch X(it+1) ----
        if (it < 11)
            xv = *reinterpret_cast<const float4*>(
                Xb + (size_t)((it + 1) * 16 + xrow) * HWSZ + xc4);

        // ---- fragments + MMA ----
        uint32_t ah[3][4], al[3][4], bh[2][4], bl[2][4];
#pragma unroll
        for (int mi = 0; mi < 3; mi++) {
            int r = wm * 48 + mi * 16 + arow;
            uint32_t addr_h = sb + (uint32_t)((OFF_WH(ws) + r * AST + acol) * 2);
            uint32_t addr_l = sb + (uint32_t)((OFF_WL(ws) + r * AST + acol) * 2);
            asm volatile("ldmatrix.sync.aligned.m8n8.x4.shared.b16 {%0,%1,%2,%3}, [%4];"
                : "=r"(ah[mi][0]), "=r"(ah[mi][1]), "=r"(ah[mi][2]), "=r"(ah[mi][3]) : "r"(addr_h));
            asm volatile("ldmatrix.sync.aligned.m8n8.x4.shared.b16 {%0,%1,%2,%3}, [%4];"
                : "=r"(al[mi][0]), "=r"(al[mi][1]), "=r"(al[mi][2]), "=r"(al[mi][3]) : "r"(addr_l));
        }
#pragma unroll
        for (int blk = 0; blk < 2; blk++) {
            int col = wn * 32 + blk * 16 + bcoff;
            uint32_t addr_h = sb + (uint32_t)((OFF_XH(xs) + brow * BST + col) * 2);
            uint32_t addr_l = sb + (uint32_t)((OFF_XL(xs) + brow * BST + col) * 2);
            asm volatile("ldmatrix.sync.aligned.m8n8.x4.trans.shared.b16 {%0,%1,%2,%3}, [%4];"
                : "=r"(bh[blk][0]), "=r"(bh[blk][1]), "=r"(bh[blk][2]), "=r"(bh[blk][3]) : "r"(addr_h));
            asm volatile("ldmatrix.sync.aligned.m8n8.x4.trans.shared.b16 {%0,%1,%2,%3}, [%4];"
                : "=r"(bl[blk][0]), "=r"(bl[blk][1]), "=r"(bl[blk][2]), "=r"(bl[blk][3]) : "r"(addr_l));
        }

#define MMA(C, A, B0, B1) \
    asm volatile("mma.sync.aligned.m16n8k16.row.col.f32.bf16.bf16.f32 " \
        "{%0,%1,%2,%3}, {%4,%5,%6,%7}, {%8,%9}, {%0,%1,%2,%3};" \
        : "+f"((C)[0]), "+f"((C)[1]), "+f"((C)[2]), "+f"((C)[3]) \
        : "r"((A)[0]), "r"((A)[1]), "r"((A)[2]), "r"((A)[3]), "r"(B0), "r"(B1))

#pragma unroll
        for (int mi = 0; mi < 3; mi++)
#pragma unroll
            for (int ni = 0; ni < 4; ni++) {
                int blk = ni >> 1, half = (ni & 1) << 1;
                MMA(acc[mi][ni], ah[mi], bh[blk][half], bh[blk][half + 1]);
                MMA(acc[mi][ni], ah[mi], bl[blk][half], bl[blk][half + 1]);
                MMA(acc[mi][ni], al[mi], bh[blk][half], bh[blk][half + 1]);
            }
        __syncthreads();
    }

    // ---- epilogue ----
    float* Yb = Y + (size_t)b * ystride_b + (size_t)nt * 192 * HWSZ + p0;
#pragma unroll
    for (int mi = 0; mi < 3; mi++) {
        int r0 = wm * 48 + mi * 16 + (lid >> 2);
#pragma unroll
        for (int ni = 0; ni < 4; ni++) {
            int px = wn * 32 + ni * 8 + (lid & 3) * 2;
            *reinterpret_cast<float2*>(Yb + (size_t)r0 * HWSZ + px) =
                make_float2(acc[mi][ni][0], acc[mi][ni][1]);
            *reinterpret_cast<float2*>(Yb + (size_t)(r0 + 8) * HWSZ + px) =
                make_float2(acc[mi][ni][2], acc[mi][ni][3]);
        }
    }
}

// ---------------- dwconv3x3 + Gram + norms + v ----------------
__device__ __forceinline__ void load_halo8v(float* halo, const float* __restrict__ src,
                                            int chBase, int ty0, int tx0, int tid) {
    for (int i = tid; i < 8 * 324; i += 256) {
        int ch  = i / 324;
        int rem = i - ch * 324;
        int r   = rem / 18;
        int cc  = rem - r * 18;
        int gy = ty0 - 1 + r, gx = tx0 - 1 + cc;
        float vv = 0.f;
        if ((unsigned)gy < 256u && (unsigned)gx < 256u)
            vv = src[(size_t)(chBase + ch) * HWSZ + gy * 256 + gx];
        halo[ch * 360 + r * 20 + cc] = vv;
    }
}

__device__ __forceinline__ float4 dw_quad(const float* hb, const float* wr) {
    float r4[4][4];
#pragma unroll
    for (int r = 0; r < 4; r++) {
        float2 a  = *reinterpret_cast<const float2*>(hb + r * 20);
        float2 b2 = *reinterpret_cast<const float2*>(hb + r * 20 + 2);
        r4[r][0] = a.x; r4[r][1] = a.y; r4[r][2] = b2.x; r4[r][3] = b2.y;
    }
    float ox = 0.f, oy = 0.f, oz = 0.f, ow = 0.f;
#pragma unroll
    for (int i2 = 0; i2 < 3; i2++)
#pragma unroll
        for (int j2 = 0; j2 < 3; j2++) {
            float wv = wr[i2 * 3 + j2];
            ox += r4[i2][j2]     * wv;
            oy += r4[i2][j2 + 1] * wv;
            oz += r4[i2 + 1][j2] * wv;
            ow += r4[i2 + 1][j2 + 1] * wv;
        }
    return make_float4(ox, oy, oz, ow);
}

__global__ __launch_bounds__(256) void dw_reduce_kernel(
    const float* __restrict__ pre_q, const float* __restrict__ pre_kv,
    const float* __restrict__ wq_dw, const float* __restrict__ wkv_dw,
    float* __restrict__ vout, float* __restrict__ ssq, float* __restrict__ ssk,
    float* __restrict__ gram)
{
    extern __shared__ float sm[];
    float* halo = sm;
    float* qs   = sm + 2880;
    float* ks   = qs + 24 * QP2;

    const int tid = threadIdx.x;
    const int b   = blockIdx.z >> 3;
    const int h   = blockIdx.z & 7;
    const int cb  = h * CH;
    const int tx0 = blockIdx.x * 16;
    const int ty0 = blockIdx.y * 16;

    const int cs = tid >> 6;
    const int qd = tid & 63;
    const int qy = qd >> 3, qx = qd & 7;
    const int hoff = (2 * qy) * 20 + 2 * qx;

    const float* srcq  = pre_q  + (size_t)b * CDIM * HWSZ;
    const float* srckv = pre_kv + (size_t)b * 2 * CDIM * HWSZ;

#pragma unroll 1
    for (int g = 0; g < 3; g++) {
        load_halo8v(halo, srcq, cb + g * 8, ty0, tx0, tid);
        __syncthreads();
#pragma unroll
        for (int it = 0; it < 2; it++) {
            int cc = cs + it * 4;
            int c  = g * 8 + cc;
            const float* w = wq_dw + (size_t)(cb + c) * 9;
            float wr[9];
#pragma unroll
            for (int j = 0; j < 9; j++) wr[j] = __ldg(w + j);
            float4 o = dw_quad(halo + cc * 360 + hoff, wr);
            *reinterpret_cast<float4*>(qs + c * QP2 + qd * 4) = o;
        }
        __syncthreads();
    }
#pragma unroll 1
    for (int g = 0; g < 3; g++) {
        load_halo8v(halo, srckv, cb + g * 8, ty0, tx0, tid);
        __syncthreads();
#pragma unroll
        for (int it = 0; it < 2; it++) {
            int cc = cs + it * 4;
            int c  = g * 8 + cc;
            const float* w = wkv_dw + (size_t)(cb + c) * 9;
            float wr[9];
#pragma unroll
            for (int j = 0; j < 9; j++) wr[j] = __ldg(w + j);
            float4 o = dw_quad(halo + cc * 360 + hoff, wr);
            *reinterpret_cast<float4*>(ks + c * QP2 + qd * 4) = o;
        }
        __syncthreads();
    }

    if (tid < 192) {
        int c = tid >> 3, s = tid & 7;
        float sq = 0.f, sk = 0.f;
#pragma unroll
        for (int i = 0; i < 8; i++) {
            int j = s + (i << 3);
            float4 a = *reinterpret_cast<const float4*>(qs + c * QP2 + 4 * j);
            sq += a.x * a.x + a.y * a.y + a.z * a.z + a.w * a.w;
            float4 kk = *reinterpret_cast<const float4*>(ks + c * QP2 + 4 * j);
            sk += kk.x * kk.x + kk.y * kk.y + kk.z * kk.z + kk.w * kk.w;
        }
#pragma unroll
        for (int off = 1; off < 8; off <<= 1) {
            sq += __shfl_xor_sync(0xffffffffu, sq, off);
            sk += __shfl_xor_sync(0xffffffffu, sk, off);
        }
        if (s == 0) {
            atomicAdd(&ssq[b * CDIM + cb + c], sq);
            atomicAdd(&ssk[b * CDIM + cb + c], sk);
        }
    }

#pragma unroll 1
    for (int t = tid; t < 288; t += 256) {
        int e = t >> 3, s = t & 7;
        int c0 = (e / 6) * 4, d0 = (e % 6) * 4;
        float acc[16];
#pragma unroll
        for (int j = 0; j < 16; j++) acc[j] = 0.f;
#pragma unroll 2
        for (int i = 0; i < 8; i++) {
            int j = s + (i << 3);
            float4 qv[4], kv[4];
#pragma unroll
            for (int r = 0; r < 4; r++) {
                qv[r] = *reinterpret_cast<const float4*>(qs + (c0 + r) * QP2 + 4 * j);
                kv[r] = *reinterpret_cast<const float4*>(ks + (d0 + r) * QP2 + 4 * j);
            }
#pragma unroll
            for (int a = 0; a < 4; a++)
#pragma unroll
                for (int d = 0; d < 4; d++)
                    acc[a * 4 + d] += qv[a].x * kv[d].x + qv[a].y * kv[d].y
                                    + qv[a].z * kv[d].z + qv[a].w * kv[d].w;
        }
#pragma unroll
        for (int off = 1; off < 8; off <<= 1)
#pragma unroll
            for (int j = 0; j < 16; j++)
                acc[j] += __shfl_xor_sync(0xffffffffu, acc[j], off);
        if (s == 0) {
            float* gb = gram + (((size_t)b * NHEADS + h) * CH + c0) * CH + d0;
#pragma unroll
            for (int jq = 0; jq < 4; jq++)
#pragma unroll
                for (int jk = 0; jk < 4; jk++)
                    atomicAdd(&gb[jq * CH + jk], acc[jq * 4 + jk]);
        }
    }

#pragma unroll 1
    for (int g = 0; g < 3; g++) {
        load_halo8v(halo, srckv, CDIM + cb + g * 8, ty0, tx0, tid);
        __syncthreads();
#pragma unroll
        for (int it = 0; it < 2; it++) {
            int cc = cs + it * 4;
            int c  = g * 8 + cc;
            const float* w = wkv_dw + (size_t)(CDIM + cb + c) * 9;
            float wr[9];
#pragma unroll
            for (int j = 0; j < 9; j++) wr[j] = __ldg(w + j);
            float4 o = dw_quad(halo + cc * 360 + hoff, wr);
            float* dst = vout + ((size_t)b * CDIM + cb + c) * HWSZ
                       + (ty0 + 2 * qy) * 256 + (tx0 + 2 * qx);
            *reinterpret_cast<float2*>(dst)       = make_float2(o.x, o.y);
            *reinterpret_cast<float2*>(dst + 256) = make_float2(o.z, o.w);
        }
        __syncthreads();
    }
}

// ---------------- softmax + M = Wproj * blockdiag(attn) ----------------
__global__ __launch_bounds__(256) void attn_proj_kernel(
    const float* __restrict__ gram, const float* __restrict__ ssq,
    const float* __restrict__ ssk,  const float* __restrict__ temp,
    const float* __restrict__ wproj, float* __restrict__ Mout)
{
    __shared__ float at[192][25];
    __shared__ float nk_s[192];
    const int b = blockIdx.x, tid = threadIdx.x;

    if (tid < 192) nk_s[tid] = fmaxf(sqrtf(ssk[b * CDIM + tid]), 1e-12f);
    __syncthreads();

    if (tid < 192) {
        int h = tid / 24, c = tid % 24;
        float nq = fmaxf(sqrtf(ssq[b * CDIM + tid]), 1e-12f);
        float tv = temp[h];
        const float* gr = gram + (((size_t)b * NHEADS + h) * CH + c) * CH;
        float vals[24];
        float mx = -1e30f;
#pragma unroll
        for (int d = 0; d < 24; d++) {
            float v = gr[d] / (nq * nk_s[h * 24 + d]) * tv;
            vals[d] = v;
            mx = fmaxf(mx, v);
        }
        float s = 0.f;
#pragma unroll
        for (int d = 0; d < 24; d++) { vals[d] = expf(vals[d] - mx); s += vals[d]; }
        float inv = 1.f / s;
#pragma unroll
        for (int d = 0; d < 24; d++) at[tid][d] = vals[d] * inv;
    }
    __syncthreads();

    for (int idx = tid; idx < 192 * 192; idx += 256) {
        int o = idx / 192, dg = idx % 192;
        int h = dg / 24, d = dg % 24;
        float s = 0.f;
#pragma unroll
        for (int c = 0; c < 24; c++)
            s += wproj[o * 192 + h * 24 + c] * at[h * 24 + c][d];
        Mout[(size_t)b * CDIM * CDIM + idx] = s;
    }
}

// ---------------- launch ----------------
extern "C" void kernel_launch(void* const* d_in, const int* in_sizes, int n_in,
                              void* d_out, int out_size) {
    const float* x      = (const float*)d_in[0];
    const float* x_ref  = (const float*)d_in[1];
    const float* wq     = (const float*)d_in[2];
    const float* wq_dw  = (const float*)d_in[3];
    const float* wkv    = (const float*)d_in[4];
    const float* wkv_dw = (const float*)d_in[5];
    const float* wproj  = (const float*)d_in[6];
    const float* temp   = (const float*)d_in[7];
    float* out = (float*)d_out;

    float *pre_q, *pre_kv, *vbuf, *gram, *ssq, *ssk, *Mm;
    __nv_bfloat16 *whq, *wlq, *whkv, *wlkv, *whm, *wlm;
    cudaGetSymbolAddress((void**)&pre_q,  g_pre_q);
    cudaGetSymbolAddress((void**)&pre_kv, g_pre_kv);
    cudaGetSymbolAddress((void**)&vbuf,   g_v);
    cudaGetSymbolAddress((void**)&gram,   g_gram);
    cudaGetSymbolAddress((void**)&ssq,    g_ssq);
    cudaGetSymbolAddress((void**)&ssk,    g_ssk);
    cudaGetSymbolAddress((void**)&Mm,     g_M);
    cudaGetSymbolAddress((void**)&whq,  g_whq);
    cudaGetSymbolAddress((void**)&wlq,  g_wlq);
    cudaGetSymbolAddress((void**)&whkv, g_whkv);
    cudaGetSymbolAddress((void**)&wlkv, g_wlkv);
    cudaGetSymbolAddress((void**)&whm,  g_whm);
    cudaGetSymbolAddress((void**)&wlm,  g_wlm);

    const int smem2 = (2880 + 2 * 24 * QP2) * (int)sizeof(float);
    cudaFuncSetAttribute(dw_reduce_kernel,
                         cudaFuncAttributeMaxDynamicSharedMemorySize, smem2);
    cudaFuncSetAttribute(hmma_gemm_kernel,
                         cudaFuncAttributeMaxDynamicSharedMemorySize, GEMM_SMEM);

    zero_stats_kernel<<<36, 256>>>(gram, ssq, ssk);

    // W -> bf16 hi/lo
    w2bf16_kernel<<<dim3(144, 1, 1), 256>>>(wq,  0LL, CDIM * CDIM, whq,  wlq,  0LL);
    w2bf16_kernel<<<dim3(288, 1, 1), 256>>>(wkv, 0LL, 2 * CDIM * CDIM, whkv, wlkv, 0LL);

    // pre_q = Wq @ x
    hmma_gemm_kernel<<<dim3(1024, 1, BSZ), 256, GEMM_SMEM>>>(
        x, (long long)CDIM * HWSZ, whq, wlq, 0LL,
        pre_q, (long long)CDIM * HWSZ);
    // pre_kv = Wkv @ x_ref
    hmma_gemm_kernel<<<dim3(1024, 2, BSZ), 256, GEMM_SMEM>>>(
        x_ref, (long long)CDIM * HWSZ, whkv, wlkv, 0LL,
        pre_kv, (long long)2 * CDIM * HWSZ);

    dw_reduce_kernel<<<dim3(16, 16, BSZ * NHEADS), 256, smem2>>>(
        pre_q, pre_kv, wq_dw, wkv_dw, vbuf, ssq, ssk, gram);

    attn_proj_kernel<<<BSZ, 256>>>(gram, ssq, ssk, temp, wproj, Mm);

    // M -> bf16 hi/lo, then out = M_b @ v
    w2bf16_kernel<<<dim3(144, 1, BSZ), 256>>>(Mm, (long long)CDIM * CDIM,
                                              CDIM * CDIM, whm, wlm,
                                              (long long)CDIM * CDIM);
    hmma_gemm_kernel<<<dim3(1024, 1, BSZ), 256, GEMM_SMEM>>>(
        vbuf, (long long)CDIM * HWSZ, whm, wlm, (long long)CDIM * CDIM,
        out, (long long)CDIM * HWSZ);
}

// round 10
// speedup vs baseline: 2.3479x; 1.0475x over previous
#include <cuda_runtime.h>
#include <cuda_fp16.h>
#include <cstdint>

#define HWSZ  65536
#define CDIM  192
#define NHEADS 8
#define CH    24
#define BSZ   2
#define QP2   260

// ---------------- scratch (no cudaMalloc allowed) ----------------
__device__ float g_pre_q [(size_t)BSZ * CDIM     * HWSZ];
__device__ float g_pre_kv[(size_t)BSZ * 2 * CDIM * HWSZ];
__device__ float g_v    [(size_t)BSZ * CDIM      * HWSZ];
__device__ float g_gram [BSZ * NHEADS * CH * CH];
__device__ float g_ssq  [BSZ * CDIM];
__device__ float g_ssk  [BSZ * CDIM];
__device__ float g_M    [BSZ * CDIM * CDIM];

// fp16 copies of the GEMM weight matrices (row-major [rows][192])
__device__ __half g_whq [CDIM * CDIM];
__device__ __half g_whkv[2 * CDIM * CDIM];
__device__ __half g_whm [BSZ * CDIM * CDIM];

__device__ __forceinline__ uint32_t smem_u32(const void* p) {
    uint32_t a;
    asm("{ .reg .u64 t; cvta.to.shared.u64 t, %1; cvt.u32.u64 %0, t; }" : "=r"(a) : "l"(p));
    return a;
}
__device__ __forceinline__ void cpa16(uint32_t dst, const void* src) {
    asm volatile("cp.async.cg.shared.global [%0], [%1], 16;" :: "r"(dst), "l"(src));
}
#define CPA_COMMIT() asm volatile("cp.async.commit_group;" ::: "memory")
#define CPA_WAIT(n)  asm volatile("cp.async.wait_group %0;" :: "n"(n) : "memory")

// ---------------- zero accumulators ----------------
__global__ void zero_stats_kernel(float* gram, float* ssq, float* ssk) {
    int i = blockIdx.x * 256 + threadIdx.x;
    if (i < BSZ * NHEADS * CH * CH) gram[i] = 0.f;
    if (i < BSZ * CDIM) { ssq[i] = 0.f; ssk[i] = 0.f; }
}

// ---------------- prep: fp32 W -> fp16 ----------------
__global__ void w2f16_kernel(const float* __restrict__ W, long long wstride_b,
                             int total, __half* __restrict__ out, long long ostride_b) {
    int b = blockIdx.z;
    int i = blockIdx.x * 256 + threadIdx.x;
    if (i >= total) return;
    out[(size_t)b * ostride_b + i] = __float2half_rn(W[(size_t)b * wstride_b + i]);
}

// ---------------- pipelined HMMA fp16 2-pass GEMM ----------------
// Y[nt*192 + m][p] = sum_k W[nt*192+m][k] * X[k][p],  K = 192.
// CTA tile BM=192, BN=64, BK=16; 8 warps (4m x 2n), warp tile 48x32.
// W: fp16, cp.async 3-stage; X: fp16 hi+lo split, reg-prefetch + STS, 2-stage.
// Per k-step per warp: 3 A-ldmatrix + 4 B-ldmatrix, 24 MMA (acc += Wh*Xh + Wh*Xl).
#define AST 24    // As row stride (halfs)
#define BST 72    // Bs row stride (halfs)
// dyn smem element offsets (half units)
#define OFF_W(s)  ((s) * 4608)
#define OFF_XH(s) (13824 + (s) * 1152)
#define OFF_XL(s) (16128 + (s) * 1152)
#define GEMM_SMEM (18432 * 2)

__global__ __launch_bounds__(256, 2) void hmma_gemm_kernel(
    const float* __restrict__ X, long long xstride_b,
    const __half* __restrict__ Wh, long long wstride_b,
    float* __restrict__ Y, long long ystride_b)
{
    extern __shared__ __half sms[];
    const uint32_t sb = smem_u32(sms);

    const int tid = threadIdx.x;
    const int lid = tid & 31;
    const int wid = tid >> 5;
    const int wm  = wid >> 1;
    const int wn  = wid & 1;
    const int p0  = blockIdx.x * 64;
    const int nt  = blockIdx.y;
    const int b   = blockIdx.z;

    const float* Xb = X + (size_t)b * xstride_b + p0;
    const __half* WhB = Wh + (size_t)b * wstride_b + (size_t)nt * 192 * 192;

    float acc[3][4][4];
#pragma unroll
    for (int i = 0; i < 3; i++)
#pragma unroll
        for (int j = 0; j < 4; j++)
#pragma unroll
            for (int r = 0; r < 4; r++) acc[i][j][r] = 0.f;

    const int xrow = tid >> 4, xc4 = (tid & 15) << 2;

    // ldmatrix lane addressing
    const int arow = (lid & 7) + ((lid >> 3) & 1) * 8;
    const int acol = (lid >> 4) * 8;
    const int brow = arow;
    const int bcoff = ((lid >> 4) & 1) * 8;

    // ---- prologue: W stages 0,1 in flight; X(0) in regs ----
    // W tile = 192 rows x 16 halfs = 384 x 16B chunks
#pragma unroll
    for (int s = 0; s < 2; s++) {
#pragma unroll
        for (int j = 0; j < 2; j++) {
            int idx = tid + j * 256;
            if (idx < 384) {
                int row = idx >> 1;
                int c8 = (idx & 1) << 3;
                cpa16(sb + (uint32_t)((OFF_W(s) + row * AST + c8) * 2),
                      WhB + (size_t)row * 192 + s * 16 + c8);
            }
        }
        CPA_COMMIT();
    }
    float4 xv = *reinterpret_cast<const float4*>(Xb + (size_t)xrow * HWSZ + xc4);

#pragma unroll 1
    for (int it = 0; it < 12; it++) {
        const int ws = it % 3;          // W stage
        const int xs = it & 1;          // X stage

        // ---- STS X(it) from regs (fp16 hi + fp16 residual lo) ----
        {
            __half hx = __float2half_rn(xv.x), hy = __float2half_rn(xv.y);
            __half hz = __float2half_rn(xv.z), hw = __float2half_rn(xv.w);
            uint32_t h01 = (uint32_t)__half_as_ushort(hx)
                         | ((uint32_t)__half_as_ushort(hy) << 16);
            uint32_t h23 = (uint32_t)__half_as_ushort(hz)
                         | ((uint32_t)__half_as_ushort(hw) << 16);
            __half lx = __float2half_rn(xv.x - __half2float(hx));
            __half ly = __float2half_rn(xv.y - __half2float(hy));
            __half lz = __float2half_rn(xv.z - __half2float(hz));
            __half lw = __float2half_rn(xv.w - __half2float(hw));
            uint32_t l01 = (uint32_t)__half_as_ushort(lx)
                         | ((uint32_t)__half_as_ushort(ly) << 16);
            uint32_t l23 = (uint32_t)__half_as_ushort(lz)
                         | ((uint32_t)__half_as_ushort(lw) << 16);
            uint32_t xh = sb + (uint32_t)((OFF_XH(xs) + xrow * BST + xc4) * 2);
            uint32_t xl = sb + (uint32_t)((OFF_XL(xs) + xrow * BST + xc4) * 2);
            asm volatile("st.shared.v2.u32 [%0], {%1, %2};" :: "r"(xh), "r"(h01), "r"(h23));
            asm volatile("st.shared.v2.u32 [%0], {%1, %2};" :: "r"(xl), "r"(l01), "r"(l23));
        }

        // ---- wait for W(it) (one newer group may stay in flight) ----
        if (it < 11) { CPA_WAIT(1); } else { CPA_WAIT(0); }
        __syncthreads();

        // ---- issue W(it+2) into stage (it+2)%3 ----
        if (it < 10) {
            int s = it + 2, ss = s % 3;
#pragma unroll
            for (int j = 0; j < 2; j++) {
                int idx = tid + j * 256;
                if (idx < 384) {
                    int row = idx >> 1;
                    int c8 = (idx & 1) << 3;
                    cpa16(sb + (uint32_t)((OFF_W(ss) + row * AST + c8) * 2),
                          WhB + (size_t)row * 192 + s * 16 + c8);
                }
            }
            CPA_COMMIT();
        }
        // ---- prefetch X(it+1) ----
        if (it < 11)
            xv = *reinterpret_cast<const float4*>(
                Xb + (size_t)((it + 1) * 16 + xrow) * HWSZ + xc4);

        // ---- fragments + MMA ----
        uint32_t ah[3][4], bh[2][4], bl[2][4];
#pragma unroll
        for (int mi = 0; mi < 3; mi++) {
            int r = wm * 48 + mi * 16 + arow;
            uint32_t addr = sb + (uint32_t)((OFF_W(ws) + r * AST + acol) * 2);
            asm volatile("ldmatrix.sync.aligned.m8n8.x4.shared.b16 {%0,%1,%2,%3}, [%4];"
                : "=r"(ah[mi][0]), "=r"(ah[mi][1]), "=r"(ah[mi][2]), "=r"(ah[mi][3]) : "r"(addr));
        }
#pragma unroll
        for (int blk = 0; blk < 2; blk++) {
            int col = wn * 32 + blk * 16 + bcoff;
            uint32_t addr_h = sb + (uint32_t)((OFF_XH(xs) + brow * BST + col) * 2);
            uint32_t addr_l = sb + (uint32_t)((OFF_XL(xs) + brow * BST + col) * 2);
            asm volatile("ldmatrix.sync.aligned.m8n8.x4.trans.shared.b16 {%0,%1,%2,%3}, [%4];"
                : "=r"(bh[blk][0]), "=r"(bh[blk][1]), "=r"(bh[blk][2]), "=r"(bh[blk][3]) : "r"(addr_h));
            asm volatile("ldmatrix.sync.aligned.m8n8.x4.trans.shared.b16 {%0,%1,%2,%3}, [%4];"
                : "=r"(bl[blk][0]), "=r"(bl[blk][1]), "=r"(bl[blk][2]), "=r"(bl[blk][3]) : "r"(addr_l));
        }

#define MMA(C, A, B0, B1) \
    asm volatile("mma.sync.aligned.m16n8k16.row.col.f32.f16.f16.f32 " \
        "{%0,%1,%2,%3}, {%4,%5,%6,%7}, {%8,%9}, {%0,%1,%2,%3};" \
        : "+f"((C)[0]), "+f"((C)[1]), "+f"((C)[2]), "+f"((C)[3]) \
        : "r"((A)[0]), "r"((A)[1]), "r"((A)[2]), "r"((A)[3]), "r"(B0), "r"(B1))

#pragma unroll
        for (int mi = 0; mi < 3; mi++)
#pragma unroll
            for (int ni = 0; ni < 4; ni++) {
                int blk = ni >> 1, half = (ni & 1) << 1;
                MMA(acc[mi][ni], ah[mi], bh[blk][half], bh[blk][half + 1]);
                MMA(acc[mi][ni], ah[mi], bl[blk][half], bl[blk][half + 1]);
            }
        __syncthreads();
    }

    // ---- epilogue ----
    float* Yb = Y + (size_t)b * ystride_b + (size_t)nt * 192 * HWSZ + p0;
#pragma unroll
    for (int mi = 0; mi < 3; mi++) {
        int r0 = wm * 48 + mi * 16 + (lid >> 2);
#pragma unroll
        for (int ni = 0; ni < 4; ni++) {
            int px = wn * 32 + ni * 8 + (lid & 3) * 2;
            *reinterpret_cast<float2*>(Yb + (size_t)r0 * HWSZ + px) =
                make_float2(acc[mi][ni][0], acc[mi][ni][1]);
            *reinterpret_cast<float2*>(Yb + (size_t)(r0 + 8) * HWSZ + px) =
                make_float2(acc[mi][ni][2], acc[mi][ni][3]);
        }
    }
}

// ---------------- dwconv3x3 + Gram + norms + v ----------------
__device__ __forceinline__ void load_halo8v(float* halo, const float* __restrict__ src,
                                            int chBase, int ty0, int tx0, int tid) {
    for (int i = tid; i < 8 * 324; i += 256) {
        int ch  = i / 324;
        int rem = i - ch * 324;
        int r   = rem / 18;
        int cc  = rem - r * 18;
        int gy = ty0 - 1 + r, gx = tx0 - 1 + cc;
        float vv = 0.f;
        if ((unsigned)gy < 256u && (unsigned)gx < 256u)
            vv = src[(size_t)(chBase + ch) * HWSZ + gy * 256 + gx];
        halo[ch * 360 + r * 20 + cc] = vv;
    }
}

__device__ __forceinline__ float4 dw_quad(const float* hb, const float* wr) {
    float r4[4][4];
#pragma unroll
    for (int r = 0; r < 4; r++) {
        float2 a  = *reinterpret_cast<const float2*>(hb + r * 20);
        float2 b2 = *reinterpret_cast<const float2*>(hb + r * 20 + 2);
        r4[r][0] = a.x; r4[r][1] = a.y; r4[r][2] = b2.x; r4[r][3] = b2.y;
    }
    float ox = 0.f, oy = 0.f, oz = 0.f, ow = 0.f;
#pragma unroll
    for (int i2 = 0; i2 < 3; i2++)
#pragma unroll
        for (int j2 = 0; j2 < 3; j2++) {
            float wv = wr[i2 * 3 + j2];
            ox += r4[i2][j2]     * wv;
            oy += r4[i2][j2 + 1] * wv;
            oz += r4[i2 + 1][j2] * wv;
            ow += r4[i2 + 1][j2 + 1] * wv;
        }
    return make_float4(ox, oy, oz, ow);
}

__global__ __launch_bounds__(256) void dw_reduce_kernel(
    const float* __restrict__ pre_q, const float* __restrict__ pre_kv,
    const float* __restrict__ wq_dw, const float* __restrict__ wkv_dw,
    float* __restrict__ vout, float* __restrict__ ssq, float* __restrict__ ssk,
    float* __restrict__ gram)
{
    extern __shared__ float sm[];
    float* halo = sm;
    float* qs   = sm + 2880;
    float* ks   = qs + 24 * QP2;

    const int tid = threadIdx.x;
    const int b   = blockIdx.z >> 3;
    const int h   = blockIdx.z & 7;
    const int cb  = h * CH;
    const int tx0 = blockIdx.x * 16;
    const int ty0 = blockIdx.y * 16;

    const int cs = tid >> 6;
    const int qd = tid & 63;
    const int qy = qd >> 3, qx = qd & 7;
    const int hoff = (2 * qy) * 20 + 2 * qx;

    const float* srcq  = pre_q  + (size_t)b * CDIM * HWSZ;
    const float* srckv = pre_kv + (size_t)b * 2 * CDIM * HWSZ;

#pragma unroll 1
    for (int g = 0; g < 3; g++) {
        load_halo8v(halo, srcq, cb + g * 8, ty0, tx0, tid);
        __syncthreads();
#pragma unroll
        for (int it = 0; it < 2; it++) {
            int cc = cs + it * 4;
            int c  = g * 8 + cc;
            const float* w = wq_dw + (size_t)(cb + c) * 9;
            float wr[9];
#pragma unroll
            for (int j = 0; j < 9; j++) wr[j] = __ldg(w + j);
            float4 o = dw_quad(halo + cc * 360 + hoff, wr);
            *reinterpret_cast<float4*>(qs + c * QP2 + qd * 4) = o;
        }
        __syncthreads();
    }
#pragma unroll 1
    for (int g = 0; g < 3; g++) {
        load_halo8v(halo, srckv, cb + g * 8, ty0, tx0, tid);
        __syncthreads();
#pragma unroll
        for (int it = 0; it < 2; it++) {
            int cc = cs + it * 4;
            int c  = g * 8 + cc;
            const float* w = wkv_dw + (size_t)(cb + c) * 9;
            float wr[9];
#pragma unroll
            for (int j = 0; j < 9; j++) wr[j] = __ldg(w + j);
            float4 o = dw_quad(halo + cc * 360 + hoff, wr);
            *reinterpret_cast<float4*>(ks + c * QP2 + qd * 4) = o;
        }
        __syncthreads();
    }

    if (tid < 192) {
        int c = tid >> 3, s = tid & 7;
        float sq = 0.f, sk = 0.f;
#pragma unroll
        for (int i = 0; i < 8; i++) {
            int j = s + (i << 3);
            float4 a = *reinterpret_cast<const float4*>(qs + c * QP2 + 4 * j);
            sq += a.x * a.x + a.y * a.y + a.z * a.z + a.w * a.w;
            float4 kk = *reinterpret_cast<const float4*>(ks + c * QP2 + 4 * j);
            sk += kk.x * kk.x + kk.y * kk.y + kk.z * kk.z + kk.w * kk.w;
        }
#pragma unroll
        for (int off = 1; off < 8; off <<= 1) {
            sq += __shfl_xor_sync(0xffffffffu, sq, off);
            sk += __shfl_xor_sync(0xffffffffu, sk, off);
        }
        if (s == 0) {
            atomicAdd(&ssq[b * CDIM + cb + c], sq);
            atomicAdd(&ssk[b * CDIM + cb + c], sk);
        }
    }

#pragma unroll 1
    for (int t = tid; t < 288; t += 256) {
        int e = t >> 3, s = t & 7;
        int c0 = (e / 6) * 4, d0 = (e % 6) * 4;
        float acc[16];
#pragma unroll
        for (int j = 0; j < 16; j++) acc[j] = 0.f;
#pragma unroll 2
        for (int i = 0; i < 8; i++) {
            int j = s + (i << 3);
            float4 qv[4], kv[4];
#pragma unroll
            for (int r = 0; r < 4; r++) {
                qv[r] = *reinterpret_cast<const float4*>(qs + (c0 + r) * QP2 + 4 * j);
                kv[r] = *reinterpret_cast<const float4*>(ks + (d0 + r) * QP2 + 4 * j);
            }
#pragma unroll
            for (int a = 0; a < 4; a++)
#pragma unroll
                for (int d = 0; d < 4; d++)
                    acc[a * 4 + d] += qv[a].x * kv[d].x + qv[a].y * kv[d].y
                                    + qv[a].z * kv[d].z + qv[a].w * kv[d].w;
        }
#pragma unroll
        for (int off = 1; off < 8; off <<= 1)
#pragma unroll
            for (int j = 0; j < 16; j++)
                acc[j] += __shfl_xor_sync(0xffffffffu, acc[j], off);
        if (s == 0) {
            float* gb = gram + (((size_t)b * NHEADS + h) * CH + c0) * CH + d0;
#pragma unroll
            for (int jq = 0; jq < 4; jq++)
#pragma unroll
                for (int jk = 0; jk < 4; jk++)
                    atomicAdd(&gb[jq * CH + jk], acc[jq * 4 + jk]);
        }
    }

#pragma unroll 1
    for (int g = 0; g < 3; g++) {
        load_halo8v(halo, srckv, CDIM + cb + g * 8, ty0, tx0, tid);
        __syncthreads();
#pragma unroll
        for (int it = 0; it < 2; it++) {
            int cc = cs + it * 4;
            int c  = g * 8 + cc;
            const float* w = wkv_dw + (size_t)(CDIM + cb + c) * 9;
            float wr[9];
#pragma unroll
            for (int j = 0; j < 9; j++) wr[j] = __ldg(w + j);
            float4 o = dw_quad(halo + cc * 360 + hoff, wr);
            float* dst = vout + ((size_t)b * CDIM + cb + c) * HWSZ
                       + (ty0 + 2 * qy) * 256 + (tx0 + 2 * qx);
            *reinterpret_cast<float2*>(dst)       = make_float2(o.x, o.y);
            *reinterpret_cast<float2*>(dst + 256) = make_float2(o.z, o.w);
        }
        __syncthreads();
    }
}

// ---------------- softmax + M = Wproj * blockdiag(attn) ----------------
__global__ __launch_bounds__(256) void attn_proj_kernel(
    const float* __restrict__ gram, const float* __restrict__ ssq,
    const float* __restrict__ ssk,  const float* __restrict__ temp,
    const float* __restrict__ wproj, float* __restrict__ Mout)
{
    __shared__ float at[192][25];
    __shared__ float nk_s[192];
    const int b = blockIdx.x, tid = threadIdx.x;

    if (tid < 192) nk_s[tid] = fmaxf(sqrtf(ssk[b * CDIM + tid]), 1e-12f);
    __syncthreads();

    if (tid < 192) {
        int h = tid / 24, c = tid % 24;
        float nq = fmaxf(sqrtf(ssq[b * CDIM + tid]), 1e-12f);
        float tv = temp[h];
        const float* gr = gram + (((size_t)b * NHEADS + h) * CH + c) * CH;
        float vals[24];
        float mx = -1e30f;
#pragma unroll
        for (int d = 0; d < 24; d++) {
            float v = gr[d] / (nq * nk_s[h * 24 + d]) * tv;
            vals[d] = v;
            mx = fmaxf(mx, v);
        }
        float s = 0.f;
#pragma unroll
        for (int d = 0; d < 24; d++) { vals[d] = expf(vals[d] - mx); s += vals[d]; }
        float inv = 1.f / s;
#pragma unroll
        for (int d = 0; d < 24; d++) at[tid][d] = vals[d] * inv;
    }
    __syncthreads();

    for (int idx = tid; idx < 192 * 192; idx += 256) {
        int o = idx / 192, dg = idx % 192;
        int h = dg / 24, d = dg % 24;
        float s = 0.f;
#pragma unroll
        for (int c = 0; c < 24; c++)
            s += wproj[o * 192 + h * 24 + c] * at[h * 24 + c][d];
        Mout[(size_t)b * CDIM * CDIM + idx] = s;
    }
}

// ---------------- launch ----------------
extern "C" void kernel_launch(void* const* d_in, const int* in_sizes, int n_in,
                              void* d_out, int out_size) {
    const float* x      = (const float*)d_in[0];
    const float* x_ref  = (const float*)d_in[1];
    const float* wq     = (const float*)d_in[2];
    const float* wq_dw  = (const float*)d_in[3];
    const float* wkv    = (const float*)d_in[4];
    const float* wkv_dw = (const float*)d_in[5];
    const float* wproj  = (const float*)d_in[6];
    const float* temp   = (const float*)d_in[7];
    float* out = (float*)d_out;

    float *pre_q, *pre_kv, *vbuf, *gram, *ssq, *ssk, *Mm;
    __half *whq, *whkv, *whm;
    cudaGetSymbolAddress((void**)&pre_q,  g_pre_q);
    cudaGetSymbolAddress((void**)&pre_kv, g_pre_kv);
    cudaGetSymbolAddress((void**)&vbuf,   g_v);
    cudaGetSymbolAddress((void**)&gram,   g_gram);
    cudaGetSymbolAddress((void**)&ssq,    g_ssq);
    cudaGetSymbolAddress((void**)&ssk,    g_ssk);
    cudaGetSymbolAddress((void**)&Mm,     g_M);
    cudaGetSymbolAddress((void**)&whq,  g_whq);
    cudaGetSymbolAddress((void**)&whkv, g_whkv);
    cudaGetSymbolAddress((void**)&whm,  g_whm);

    const int smem2 = (2880 + 2 * 24 * QP2) * (int)sizeof(float);
    cudaFuncSetAttribute(dw_reduce_kernel,
                         cudaFuncAttributeMaxDynamicSharedMemorySize, smem2);
    cudaFuncSetAttribute(hmma_gemm_kernel,
                         cudaFuncAttributeMaxDynamicSharedMemorySize, GEMM_SMEM);

    zero_stats_kernel<<<36, 256>>>(gram, ssq, ssk);

    // W -> fp16
    w2f16_kernel<<<dim3(144, 1, 1), 256>>>(wq,  0LL, CDIM * CDIM, whq,  0LL);
    w2f16_kernel<<<dim3(288, 1, 1), 256>>>(wkv, 0LL, 2 * CDIM * CDIM, whkv, 0LL);

    // pre_q = Wq @ x
    hmma_gemm_kernel<<<dim3(1024, 1, BSZ), 256, GEMM_SMEM>>>(
        x, (long long)CDIM * HWSZ, whq, 0LL,
        pre_q, (long long)CDIM * HWSZ);
    // pre_kv = Wkv @ x_ref
    hmma_gemm_kernel<<<dim3(1024, 2, BSZ), 256, GEMM_SMEM>>>(
        x_ref, (long long)CDIM * HWSZ, whkv, 0LL,
        pre_kv, (long long)2 * CDIM * HWSZ);

    dw_reduce_kernel<<<dim3(16, 16, BSZ * NHEADS), 256, smem2>>>(
        pre_q, pre_kv, wq_dw, wkv_dw, vbuf, ssq, ssk, gram);

    attn_proj_kernel<<<BSZ, 256>>>(gram, ssq, ssk, temp, wproj, Mm);

    // M -> fp16, then out = M_b @ v
    w2f16_kernel<<<dim3(144, 1, BSZ), 256>>>(Mm, (long long)CDIM * CDIM,
                                             CDIM * CDIM, whm,
                                             (long long)CDIM * CDIM);
    hmma_gemm_kernel<<<dim3(1024, 1, BSZ), 256, GEMM_SMEM>>>(
        vbuf, (long long)CDIM * HWSZ, whm, (long long)CDIM * CDIM,
        out, (long long)CDIM * HWSZ);
}

// round 11
// speedup vs baseline: 2.7489x; 1.1708x over previous
#include <cuda_runtime.h>
#include <cuda_fp16.h>
#include <cstdint>

#define HWSZ  65536
#define CDIM  192
#define NHEADS 8
#define CH    24
#define BSZ   2
#define QP2   260

// ---------------- scratch (no cudaMalloc allowed) ----------------
__device__ float g_pre  [(size_t)BSZ * 3 * CDIM * HWSZ];   // q (nt0) + kv (nt1,2)
__device__ float g_v    [(size_t)BSZ * CDIM     * HWSZ];
__device__ float g_gram [BSZ * NHEADS * CH * CH];
__device__ float g_ssq  [BSZ * CDIM];
__device__ float g_ssk  [BSZ * CDIM];
__device__ float g_M    [BSZ * CDIM * CDIM];

// fp16 weights: slot 0 = wq, slots 1,2 = wkv   (row-major [rows][192])
__device__ __half g_wqkv[3 * CDIM * CDIM];
__device__ __half g_whm [BSZ * CDIM * CDIM];

__device__ __forceinline__ uint32_t smem_u32(const void* p) {
    uint32_t a;
    asm("{ .reg .u64 t; cvta.to.shared.u64 t, %1; cvt.u32.u64 %0, t; }" : "=r"(a) : "l"(p));
    return a;
}
__device__ __forceinline__ void cpa16(uint32_t dst, const void* src) {
    asm volatile("cp.async.cg.shared.global [%0], [%1], 16;" :: "r"(dst), "l"(src));
}
#define CPA_COMMIT() asm volatile("cp.async.commit_group;" ::: "memory")
#define CPA_WAIT(n)  asm volatile("cp.async.wait_group %0;" :: "n"(n) : "memory")

// ---------------- zero accumulators ----------------
__global__ void zero_stats_kernel(float* gram, float* ssq, float* ssk) {
    int i = blockIdx.x * 256 + threadIdx.x;
    if (i < BSZ * NHEADS * CH * CH) gram[i] = 0.f;
    if (i < BSZ * CDIM) { ssq[i] = 0.f; ssk[i] = 0.f; }
}

// ---------------- prep: fp32 W -> fp16 ----------------
__global__ void w2f16_kernel(const float* __restrict__ W, long long wstride_b,
                             int total, __half* __restrict__ out, long long ostride_b) {
    int b = blockIdx.z;
    int i = blockIdx.x * 256 + threadIdx.x;
    if (i >= total) return;
    out[(size_t)b * ostride_b + i] = __float2half_rn(W[(size_t)b * wstride_b + i]);
}

// ---------------- pipelined HMMA fp16 2-pass GEMM, BK=32 ----------------
// Y[nt*192 + m][p] = sum_k W[nt*192+m][k] * X[k][p],  K = 192, 6 k-iters.
// CTA tile BM=192, BN=64, BK=32; 8 warps (4m x 2n), warp tile 48x32.
// W: fp16, cp.async 3-stage; X: fp16 hi+lo split, reg-prefetch + STS, 2-stage.
#define AST 40    // As row stride (halfs): 80B, conflict-free ldmatrix
#define BST 72    // Bs row stride (halfs)
// dyn smem element offsets (half units)
#define OFF_W(s)  ((s) * 7680)                      // 192*40 per stage
#define OFF_XH(s) (23040 + (s) * 4608)              // 32*72 hi
#define OFF_XL(s) (23040 + (s) * 4608 + 2304)       // 32*72 lo
#define GEMM_SMEM (32256 * 2)                       // 64512 B

__global__ __launch_bounds__(256, 2) void hmma_gemm_kernel(
    const float* __restrict__ X, long long xstride_b,
    const __half* __restrict__ Wh, long long wstride_b,
    float* __restrict__ Y, long long ystride_b)
{
    extern __shared__ __half sms[];
    const uint32_t sb = smem_u32(sms);

    const int tid = threadIdx.x;
    const int lid = tid & 31;
    const int wid = tid >> 5;
    const int wm  = wid >> 1;
    const int wn  = wid & 1;
    const int p0  = blockIdx.x * 64;
    const int nt  = blockIdx.y;
    const int b   = blockIdx.z;

    const float* Xb = X + (size_t)b * xstride_b + p0;
    const __half* WhB = Wh + (size_t)b * wstride_b + (size_t)nt * 192 * 192;

    float acc[3][4][4];
#pragma unroll
    for (int i = 0; i < 3; i++)
#pragma unroll
        for (int j = 0; j < 4; j++)
#pragma unroll
            for (int r = 0; r < 4; r++) acc[i][j][r] = 0.f;

    const int xrow = tid >> 4, xc4 = (tid & 15) << 2;

    // ldmatrix lane addressing
    const int arow = (lid & 7) + ((lid >> 3) & 1) * 8;
    const int acol = (lid >> 4) * 8;
    const int brow = arow;
    const int bcoff = ((lid >> 4) & 1) * 8;

    // ---- prologue: W stages 0,1 in flight; X(0) in regs ----
    // W tile = 192 rows x 32 halfs = 768 x 16B chunks, 3 per thread
#pragma unroll
    for (int s = 0; s < 2; s++) {
#pragma unroll
        for (int j = 0; j < 3; j++) {
            int idx = tid + j * 256;
            int row = idx >> 2;
            int c8  = (idx & 3) << 3;
            cpa16(sb + (uint32_t)((OFF_W(s) + row * AST + c8) * 2),
                  WhB + (size_t)row * 192 + s * 32 + c8);
        }
        CPA_COMMIT();
    }
    float4 xv0 = *reinterpret_cast<const float4*>(Xb + (size_t)xrow * HWSZ + xc4);
    float4 xv1 = *reinterpret_cast<const float4*>(Xb + (size_t)(xrow + 16) * HWSZ + xc4);

#pragma unroll 1
    for (int it = 0; it < 6; it++) {
        const int ws = it % 3;          // W stage
        const int xs = it & 1;          // X stage

        // ---- STS X(it): rows xrow and xrow+16, fp16 hi + residual lo ----
#pragma unroll
        for (int half2 = 0; half2 < 2; half2++) {
            float4 v = half2 ? xv1 : xv0;
            int row = xrow + half2 * 16;
            __half hx = __float2half_rn(v.x), hy = __float2half_rn(v.y);
            __half hz = __float2half_rn(v.z), hw = __float2half_rn(v.w);
            uint32_t h01 = (uint32_t)__half_as_ushort(hx)
                         | ((uint32_t)__half_as_ushort(hy) << 16);
            uint32_t h23 = (uint32_t)__half_as_ushort(hz)
                         | ((uint32_t)__half_as_ushort(hw) << 16);
            __half lx = __float2half_rn(v.x - __half2float(hx));
            __half ly = __float2half_rn(v.y - __half2float(hy));
            __half lz = __float2half_rn(v.z - __half2float(hz));
            __half lw = __float2half_rn(v.w - __half2float(hw));
            uint32_t l01 = (uint32_t)__half_as_ushort(lx)
                         | ((uint32_t)__half_as_ushort(ly) << 16);
            uint32_t l23 = (uint32_t)__half_as_ushort(lz)
                         | ((uint32_t)__half_as_ushort(lw) << 16);
            uint32_t xh = sb + (uint32_t)((OFF_XH(xs) + row * BST + xc4) * 2);
            uint32_t xl = sb + (uint32_t)((OFF_XL(xs) + row * BST + xc4) * 2);
            asm volatile("st.shared.v2.u32 [%0], {%1, %2};" :: "r"(xh), "r"(h01), "r"(h23));
            asm volatile("st.shared.v2.u32 [%0], {%1, %2};" :: "r"(xl), "r"(l01), "r"(l23));
        }

        // ---- wait for W(it) (one newer group may stay in flight) ----
        if (it < 5) { CPA_WAIT(1); } else { CPA_WAIT(0); }
        __syncthreads();

        // ---- issue W(it+2) into stage (it+2)%3 ----
        if (it < 4) {
            int s = it + 2, ss = s % 3;
#pragma unroll
            for (int j = 0; j < 3; j++) {
                int idx = tid + j * 256;
                int row = idx >> 2;
                int c8  = (idx & 3) << 3;
                cpa16(sb + (uint32_t)((OFF_W(ss) + row * AST + c8) * 2),
                      WhB + (size_t)row * 192 + s * 32 + c8);
            }
            CPA_COMMIT();
        }
        // ---- prefetch X(it+1) ----
        if (it < 5) {
            xv0 = *reinterpret_cast<const float4*>(
                Xb + (size_t)((it + 1) * 32 + xrow) * HWSZ + xc4);
            xv1 = *reinterpret_cast<const float4*>(
                Xb + (size_t)((it + 1) * 32 + xrow + 16) * HWSZ + xc4);
        }

        // ---- fragments + MMA (two k-halves) ----
        uint32_t ah[2][3][4], bh[2][2][4], bl[2][2][4];
#pragma unroll
        for (int kh = 0; kh < 2; kh++) {
#pragma unroll
            for (int mi = 0; mi < 3; mi++) {
                int r = wm * 48 + mi * 16 + arow;
                uint32_t addr = sb + (uint32_t)((OFF_W(ws) + r * AST + kh * 16 + acol) * 2);
                asm volatile("ldmatrix.sync.aligned.m8n8.x4.shared.b16 {%0,%1,%2,%3}, [%4];"
                    : "=r"(ah[kh][mi][0]), "=r"(ah[kh][mi][1]),
                      "=r"(ah[kh][mi][2]), "=r"(ah[kh][mi][3]) : "r"(addr));
            }
#pragma unroll
            for (int blk = 0; blk < 2; blk++) {
                int col = wn * 32 + blk * 16 + bcoff;
                int krow = kh * 16 + brow;
                uint32_t addr_h = sb + (uint32_t)((OFF_XH(xs) + krow * BST + col) * 2);
                uint32_t addr_l = sb + (uint32_t)((OFF_XL(xs) + krow * BST + col) * 2);
                asm volatile("ldmatrix.sync.aligned.m8n8.x4.trans.shared.b16 {%0,%1,%2,%3}, [%4];"
                    : "=r"(bh[kh][blk][0]), "=r"(bh[kh][blk][1]),
                      "=r"(bh[kh][blk][2]), "=r"(bh[kh][blk][3]) : "r"(addr_h));
                asm volatile("ldmatrix.sync.aligned.m8n8.x4.trans.shared.b16 {%0,%1,%2,%3}, [%4];"
                    : "=r"(bl[kh][blk][0]), "=r"(bl[kh][blk][1]),
                      "=r"(bl[kh][blk][2]), "=r"(bl[kh][blk][3]) : "r"(addr_l));
            }
        }

#define MMA(C, A, B0, B1) \
    asm volatile("mma.sync.aligned.m16n8k16.row.col.f32.f16.f16.f32 " \
        "{%0,%1,%2,%3}, {%4,%5,%6,%7}, {%8,%9}, {%0,%1,%2,%3};" \
        : "+f"((C)[0]), "+f"((C)[1]), "+f"((C)[2]), "+f"((C)[3]) \
        : "r"((A)[0]), "r"((A)[1]), "r"((A)[2]), "r"((A)[3]), "r"(B0), "r"(B1))

#pragma unroll
        for (int kh = 0; kh < 2; kh++)
#pragma unroll
            for (int mi = 0; mi < 3; mi++)
#pragma unroll
                for (int ni = 0; ni < 4; ni++) {
                    int blk = ni >> 1, half = (ni & 1) << 1;
                    MMA(acc[mi][ni], ah[kh][mi], bh[kh][blk][half], bh[kh][blk][half + 1]);
                    MMA(acc[mi][ni], ah[kh][mi], bl[kh][blk][half], bl[kh][blk][half + 1]);
                }
        __syncthreads();
    }

    // ---- epilogue ----
    float* Yb = Y + (size_t)b * ystride_b + (size_t)nt * 192 * HWSZ + p0;
#pragma unroll
    for (int mi = 0; mi < 3; mi++) {
        int r0 = wm * 48 + mi * 16 + (lid >> 2);
#pragma unroll
        for (int ni = 0; ni < 4; ni++) {
            int px = wn * 32 + ni * 8 + (lid & 3) * 2;
            *reinterpret_cast<float2*>(Yb + (size_t)r0 * HWSZ + px) =
                make_float2(acc[mi][ni][0], acc[mi][ni][1]);
            *reinterpret_cast<float2*>(Yb + (size_t)(r0 + 8) * HWSZ + px) =
                make_float2(acc[mi][ni][2], acc[mi][ni][3]);
        }
    }
}

// ---------------- dwconv3x3 + Gram + norms + v ----------------
__device__ __forceinline__ void load_halo8v(float* halo, const float* __restrict__ src,
                                            int chBase, int ty0, int tx0, int tid) {
    for (int i = tid; i < 8 * 324; i += 256) {
        int ch  = i / 324;
        int rem = i - ch * 324;
        int r   = rem / 18;
        int cc  = rem - r * 18;
        int gy = ty0 - 1 + r, gx = tx0 - 1 + cc;
        float vv = 0.f;
        if ((unsigned)gy < 256u && (unsigned)gx < 256u)
            vv = src[(size_t)(chBase + ch) * HWSZ + gy * 256 + gx];
        halo[ch * 360 + r * 20 + cc] = vv;
    }
}

__device__ __forceinline__ float4 dw_quad(const float* hb, const float* wr) {
    float r4[4][4];
#pragma unroll
    for (int r = 0; r < 4; r++) {
        float2 a  = *reinterpret_cast<const float2*>(hb + r * 20);
        float2 b2 = *reinterpret_cast<const float2*>(hb + r * 20 + 2);
        r4[r][0] = a.x; r4[r][1] = a.y; r4[r][2] = b2.x; r4[r][3] = b2.y;
    }
    float ox = 0.f, oy = 0.f, oz = 0.f, ow = 0.f;
#pragma unroll
    for (int i2 = 0; i2 < 3; i2++)
#pragma unroll
        for (int j2 = 0; j2 < 3; j2++) {
            float wv = wr[i2 * 3 + j2];
            ox += r4[i2][j2]     * wv;
            oy += r4[i2][j2 + 1] * wv;
            oz += r4[i2 + 1][j2] * wv;
            ow += r4[i2 + 1][j2 + 1] * wv;
        }
    return make_float4(ox, oy, oz, ow);
}

__global__ __launch_bounds__(256) void dw_reduce_kernel(
    const float* __restrict__ pre, const float* __restrict__ wq_dw,
    const float* __restrict__ wkv_dw,
    float* __restrict__ vout, float* __restrict__ ssq, float* __restrict__ ssk,
    float* __restrict__ gram)
{
    extern __shared__ float sm[];
    float* halo = sm;
    float* qs   = sm + 2880;
    float* ks   = qs + 24 * QP2;

    const int tid = threadIdx.x;
    const int b   = blockIdx.z >> 3;
    const int h   = blockIdx.z & 7;
    const int cb  = h * CH;
    const int tx0 = blockIdx.x * 16;
    const int ty0 = blockIdx.y * 16;

    const int cs = tid >> 6;
    const int qd = tid & 63;
    const int qy = qd >> 3, qx = qd & 7;
    const int hoff = (2 * qy) * 20 + 2 * qx;

    const float* srcq  = pre + (size_t)b * 3 * CDIM * HWSZ;
    const float* srckv = srcq + (size_t)CDIM * HWSZ;

#pragma unroll 1
    for (int g = 0; g < 3; g++) {
        load_halo8v(halo, srcq, cb + g * 8, ty0, tx0, tid);
        __syncthreads();
#pragma unroll
        for (int it = 0; it < 2; it++) {
            int cc = cs + it * 4;
            int c  = g * 8 + cc;
            const float* w = wq_dw + (size_t)(cb + c) * 9;
            float wr[9];
#pragma unroll
            for (int j = 0; j < 9; j++) wr[j] = __ldg(w + j);
            float4 o = dw_quad(halo + cc * 360 + hoff, wr);
            *reinterpret_cast<float4*>(qs + c * QP2 + qd * 4) = o;
        }
        __syncthreads();
    }
#pragma unroll 1
    for (int g = 0; g < 3; g++) {
        load_halo8v(halo, srckv, cb + g * 8, ty0, tx0, tid);
        __syncthreads();
#pragma unroll
        for (int it = 0; it < 2; it++) {
            int cc = cs + it * 4;
            int c  = g * 8 + cc;
            const float* w = wkv_dw + (size_t)(cb + c) * 9;
            float wr[9];
#pragma unroll
            for (int j = 0; j < 9; j++) wr[j] = __ldg(w + j);
            float4 o = dw_quad(halo + cc * 360 + hoff, wr);
            *reinterpret_cast<float4*>(ks + c * QP2 + qd * 4) = o;
        }
        __syncthreads();
    }

    if (tid < 192) {
        int c = tid >> 3, s = tid & 7;
        float sq = 0.f, sk = 0.f;
#pragma unroll
        for (int i = 0; i < 8; i++) {
            int j = s + (i << 3);
            float4 a = *reinterpret_cast<const float4*>(qs + c * QP2 + 4 * j);
            sq += a.x * a.x + a.y * a.y + a.z * a.z + a.w * a.w;
            float4 kk = *reinterpret_cast<const float4*>(ks + c * QP2 + 4 * j);
            sk += kk.x * kk.x + kk.y * kk.y + kk.z * kk.z + kk.w * kk.w;
        }
#pragma unroll
        for (int off = 1; off < 8; off <<= 1) {
            sq += __shfl_xor_sync(0xffffffffu, sq, off);
            sk += __shfl_xor_sync(0xffffffffu, sk, off);
        }
        if (s == 0) {
            atomicAdd(&ssq[b * CDIM + cb + c], sq);
            atomicAdd(&ssk[b * CDIM + cb + c], sk);
        }
    }

#pragma unroll 1
    for (int t = tid; t < 288; t += 256) {
        int e = t >> 3, s = t & 7;
        int c0 = (e / 6) * 4, d0 = (e % 6) * 4;
        float acc[16];
#pragma unroll
        for (int j = 0; j < 16; j++) acc[j] = 0.f;
#pragma unroll 2
        for (int i = 0; i < 8; i++) {
            int j = s + (i << 3);
            float4 qv[4], kv[4];
#pragma unroll
            for (int r = 0; r < 4; r++) {
                qv[r] = *reinterpret_cast<const float4*>(qs + (c0 + r) * QP2 + 4 * j);
                kv[r] = *reinterpret_cast<const float4*>(ks + (d0 + r) * QP2 + 4 * j);
            }
#pragma unroll
            for (int a = 0; a < 4; a++)
#pragma unroll
                for (int d = 0; d < 4; d++)
                    acc[a * 4 + d] += qv[a].x * kv[d].x + qv[a].y * kv[d].y
                                    + qv[a].z * kv[d].z + qv[a].w * kv[d].w;
        }
#pragma unroll
        for (int off = 1; off < 8; off <<= 1)
#pragma unroll
            for (int j = 0; j < 16; j++)
                acc[j] += __shfl_xor_sync(0xffffffffu, acc[j], off);
        if (s == 0) {
            float* gb = gram + (((size_t)b * NHEADS + h) * CH + c0) * CH + d0;
#pragma unroll
            for (int jq = 0; jq < 4; jq++)
#pragma unroll
                for (int jk = 0; jk < 4; jk++)
                    atomicAdd(&gb[jq * CH + jk], acc[jq * 4 + jk]);
        }
    }

#pragma unroll 1
    for (int g = 0; g < 3; g++) {
        load_halo8v(halo, srckv, CDIM + cb + g * 8, ty0, tx0, tid);
        __syncthreads();
#pragma unroll
        for (int it = 0; it < 2; it++) {
            int cc = cs + it * 4;
            int c  = g * 8 + cc;
            const float* w = wkv_dw + (size_t)(CDIM + cb + c) * 9;
            float wr[9];
#pragma unroll
            for (int j = 0; j < 9; j++) wr[j] = __ldg(w + j);
            float4 o = dw_quad(halo + cc * 360 + hoff, wr);
            float* dst = vout + ((size_t)b * CDIM + cb + c) * HWSZ
                       + (ty0 + 2 * qy) * 256 + (tx0 + 2 * qx);
            *reinterpret_cast<float2*>(dst)       = make_float2(o.x, o.y);
            *reinterpret_cast<float2*>(dst + 256) = make_float2(o.z, o.w);
        }
        __syncthreads();
    }
}

// ---------------- softmax + M = Wproj * blockdiag(attn) ----------------
__global__ __launch_bounds__(256) void attn_proj_kernel(
    const float* __restrict__ gram, const float* __restrict__ ssq,
    const float* __restrict__ ssk,  const float* __restrict__ temp,
    const float* __restrict__ wproj, float* __restrict__ Mout)
{
    __shared__ float at[192][25];
    __shared__ float nk_s[192];
    const int b = blockIdx.x, tid = threadIdx.x;

    if (tid < 192) nk_s[tid] = fmaxf(sqrtf(ssk[b * CDIM + tid]), 1e-12f);
    __syncthreads();

    if (tid < 192) {
        int h = tid / 24, c = tid % 24;
        float nq = fmaxf(sqrtf(ssq[b * CDIM + tid]), 1e-12f);
        float tv = temp[h];
        const float* gr = gram + (((size_t)b * NHEADS + h) * CH + c) * CH;
        float vals[24];
        float mx = -1e30f;
#pragma unroll
        for (int d = 0; d < 24; d++) {
            float v = gr[d] / (nq * nk_s[h * 24 + d]) * tv;
            vals[d] = v;
            mx = fmaxf(mx, v);
        }
        float s = 0.f;
#pragma unroll
        for (int d = 0; d < 24; d++) { vals[d] = expf(vals[d] - mx); s += vals[d]; }
        float inv = 1.f / s;
#pragma unroll
        for (int d = 0; d < 24; d++) at[tid][d] = vals[d] * inv;
    }
    __syncthreads();

    for (int idx = tid; idx < 192 * 192; idx += 256) {
        int o = idx / 192, dg = idx % 192;
        int h = dg / 24, d = dg % 24;
        float s = 0.f;
#pragma unroll
        for (int c = 0; c < 24; c++)
            s += wproj[o * 192 + h * 24 + c] * at[h * 24 + c][d];
        Mout[(size_t)b * CDIM * CDIM + idx] = s;
    }
}

// ---------------- launch ----------------
extern "C" void kernel_launch(void* const* d_in, const int* in_sizes, int n_in,
                              void* d_out, int out_size) {
    const float* x      = (const float*)d_in[0];
    const float* x_ref  = (const float*)d_in[1];
    const float* wq     = (const float*)d_in[2];
    const float* wq_dw  = (const float*)d_in[3];
    const float* wkv    = (const float*)d_in[4];
    const float* wkv_dw = (const float*)d_in[5];
    const float* wproj  = (const float*)d_in[6];
    const float* temp   = (const float*)d_in[7];
    float* out = (float*)d_out;

    float *pre, *vbuf, *gram, *ssq, *ssk, *Mm;
    __half *wqkv, *whm;
    cudaGetSymbolAddress((void**)&pre,  g_pre);
    cudaGetSymbolAddress((void**)&vbuf, g_v);
    cudaGetSymbolAddress((void**)&gram, g_gram);
    cudaGetSymbolAddress((void**)&ssq,  g_ssq);
    cudaGetSymbolAddress((void**)&ssk,  g_ssk);
    cudaGetSymbolAddress((void**)&Mm,   g_M);
    cudaGetSymbolAddress((void**)&wqkv, g_wqkv);
    cudaGetSymbolAddress((void**)&whm,  g_whm);

    const int smem2 = (2880 + 2 * 24 * QP2) * (int)sizeof(float);
    cudaFuncSetAttribute(dw_reduce_kernel,
                         cudaFuncAttributeMaxDynamicSharedMemorySize, smem2);
    cudaFuncSetAttribute(hmma_gemm_kernel,
                         cudaFuncAttributeMaxDynamicSharedMemorySize, GEMM_SMEM);

    zero_stats_kernel<<<36, 256>>>(gram, ssq, ssk);

    // W -> fp16: wq into slot 0, wkv into slots 1,2
    w2f16_kernel<<<dim3(144, 1, 1), 256>>>(wq,  0LL, CDIM * CDIM, wqkv, 0LL);
    w2f16_kernel<<<dim3(288, 1, 1), 256>>>(wkv, 0LL, 2 * CDIM * CDIM,
                                           wqkv + CDIM * CDIM, 0LL);

    // q + kv in ONE launch: x feeds nt 0, x_ref feeds nt 1,2 — but X differs per nt.
    // Trick: nt 0 reads x, nt 1,2 read x_ref. Use two launches only if X must differ;
    // instead pass x and x_ref... X pointer differs by nt, so keep two launches but
    // both write into the contiguous g_pre buffer (no separate q buffer).
    hmma_gemm_kernel<<<dim3(1024, 1, BSZ), 256, GEMM_SMEM>>>(
        x, (long long)CDIM * HWSZ, wqkv, 0LL,
        pre, (long long)3 * CDIM * HWSZ);
    hmma_gemm_kernel<<<dim3(1024, 2, BSZ), 256, GEMM_SMEM>>>(
        x_ref, (long long)CDIM * HWSZ, wqkv + CDIM * CDIM, 0LL,
        pre + (size_t)CDIM * HWSZ, (long long)3 * CDIM * HWSZ);

    dw_reduce_kernel<<<dim3(16, 16, BSZ * NHEADS), 256, smem2>>>(
        pre, wq_dw, wkv_dw, vbuf, ssq, ssk, gram);

    attn_proj_kernel<<<BSZ, 256>>>(gram, ssq, ssk, temp, wproj, Mm);

    // M -> fp16, then out = M_b @ v
    w2f16_kernel<<<dim3(144, 1, BSZ), 256>>>(Mm, (long long)CDIM * CDIM,
                                             CDIM * CDIM, whm,
                                             (long long)CDIM * CDIM);
    hmma_gemm_kernel<<<dim3(1024, 1, BSZ), 256, GEMM_SMEM>>>(
        vbuf, (long long)CDIM * HWSZ, whm, (long long)CDIM * CDIM,
        out, (long long)CDIM * HWSZ);
}